// round 2
// baseline (speedup 1.0000x reference)
#include <cuda_runtime.h>
#include <math.h>

#define BB   2
#define SS   2048
#define DD   1024
#define HH   16
#define HDIM 64
#define FFND 2048
#define NE   8
#define CAPN 1280
#define TT   (BB*SS)      /* 4096 tokens */
#define NS   (TT*2)       /* 8192 slots  */

// ---------------- scratch (device globals; no allocations) ----------------
__device__ float g_xn  [TT*DD];
__device__ float g_qkv [TT*3*DD];
__device__ float g_attn[TT*DD];
__device__ float g_x1  [TT*DD];
__device__ float g_xn2 [TT*DD];
__device__ int   g_fe  [NS];
__device__ float g_fg  [NS];
__device__ int   g_cnt [NE];
__device__ int   g_esl [NE*NS];
__device__ float g_egt [NE*NS];
__device__ int   g_dtok[NE*CAPN];
__device__ int   g_srow[NS];
__device__ float g_xe  [NE*CAPN*DD];
__device__ float g_h   [NE*CAPN*FFND];
__device__ float g_ye  [NE*CAPN*DD];

// ---------------- rmsnorm: one block per token ----------------
__global__ void rmsnorm_k(const float* __restrict__ in, const float* __restrict__ g,
                          float* __restrict__ out) {
    int t = blockIdx.x;
    const float4* xi = (const float4*)(in + (size_t)t * DD);
    float4 v = xi[threadIdx.x];
    float ss = v.x*v.x + v.y*v.y + v.z*v.z + v.w*v.w;
    __shared__ float red[256];
    red[threadIdx.x] = ss;
    __syncthreads();
    for (int s = 128; s > 0; s >>= 1) {
        if (threadIdx.x < s) red[threadIdx.x] += red[threadIdx.x + s];
        __syncthreads();
    }
    float rms = rsqrtf(red[0] / (float)DD + 1e-6f);
    float4 gv = ((const float4*)g)[threadIdx.x];
    float4 o;
    o.x = v.x * gv.x * rms; o.y = v.y * gv.y * rms;
    o.z = v.z * gv.z * rms; o.w = v.w * gv.w * rms;
    ((float4*)(out + (size_t)t * DD))[threadIdx.x] = o;
}

// ---------------- generic 64x64 tiled fp32 GEMM (optionally batched / relu / addend) --
__global__ __launch_bounds__(256) void gemm_k(
    const float* __restrict__ A, const float* __restrict__ B, float* __restrict__ C,
    const float* __restrict__ addend, int M, int N, int K,
    long long sA, long long sB, long long sC, int relu)
{
    int e = blockIdx.z;
    A += (size_t)e * sA; B += (size_t)e * sB; C += (size_t)e * sC;
    __shared__ float As[16][64];
    __shared__ float Bs[16][64];
    int tx = threadIdx.x & 15, ty = threadIdx.x >> 4;
    int rowb = blockIdx.y * 64, colb = blockIdx.x * 64;
    float acc[4][4];
    #pragma unroll
    for (int i = 0; i < 4; i++)
        #pragma unroll
        for (int j = 0; j < 4; j++) acc[i][j] = 0.f;

    int ar  = threadIdx.x >> 2, ac4 = threadIdx.x & 3;
    int br  = threadIdx.x >> 4, bc4 = threadIdx.x & 15;

    for (int k0 = 0; k0 < K; k0 += 16) {
        float4 av = *(const float4*)(A + (size_t)(rowb + ar) * K + k0 + ac4 * 4);
        float4 bv = *(const float4*)(B + (size_t)(k0 + br) * N + colb + bc4 * 4);
        __syncthreads();
        As[ac4*4+0][ar] = av.x; As[ac4*4+1][ar] = av.y;
        As[ac4*4+2][ar] = av.z; As[ac4*4+3][ar] = av.w;
        *(float4*)&Bs[br][bc4*4] = bv;
        __syncthreads();
        #pragma unroll
        for (int kk = 0; kk < 16; kk++) {
            float4 a = *(const float4*)&As[kk][ty*4];
            float4 b = *(const float4*)&Bs[kk][tx*4];
            acc[0][0] += a.x*b.x; acc[0][1] += a.x*b.y; acc[0][2] += a.x*b.z; acc[0][3] += a.x*b.w;
            acc[1][0] += a.y*b.x; acc[1][1] += a.y*b.y; acc[1][2] += a.y*b.z; acc[1][3] += a.y*b.w;
            acc[2][0] += a.z*b.x; acc[2][1] += a.z*b.y; acc[2][2] += a.z*b.z; acc[2][3] += a.z*b.w;
            acc[3][0] += a.w*b.x; acc[3][1] += a.w*b.y; acc[3][2] += a.w*b.z; acc[3][3] += a.w*b.w;
        }
    }
    #pragma unroll
    for (int i = 0; i < 4; i++)
        #pragma unroll
        for (int j = 0; j < 4; j++) {
            size_t idx = (size_t)(rowb + ty*4 + i) * N + colb + tx*4 + j;
            float v = acc[i][j];
            if (addend) v += addend[idx];
            if (relu)   v = fmaxf(v, 0.f);
            C[idx] = v;
        }
}

// ---------------- RoPE in-place on q,k halves of qkv ----------------
__global__ void rope_k(float* __restrict__ qkv) {
    int t = blockIdx.x;
    int s = t % SS;
    for (int w = threadIdx.x; w < 1024; w += blockDim.x) {
        int which = w >> 9;        // 0 = q, 1 = k
        int rem   = w & 511;
        int h     = rem >> 5;
        int i     = rem & 31;
        float theta = exp2f(-(float)i * 0.41524101186092030f);  // 10000^{-i/32}
        float fr = (float)s * theta;
        float c = cosf(fr), sn = sinf(fr);
        size_t base = (size_t)t * (3*DD) + (size_t)which * DD + h * HDIM + 2*i;
        float xr = qkv[base], xi = qkv[base+1];
        qkv[base]   = xr*c - xi*sn;
        qkv[base+1] = xr*sn + xi*c;
    }
}

// ---------------- causal flash attention: 1 query per thread, 64 q per block ----
__global__ __launch_bounds__(64) void attn_k(const float* __restrict__ qkv,
                                             float* __restrict__ out) {
    int qt = blockIdx.x;           // q tile (64 queries)
    int bh = blockIdx.y;
    int b = bh / HH, h = bh % HH;
    int tid = threadIdx.x;
    int qg = qt * 64 + tid;

    const size_t RS = 3 * DD;
    const float scale = 0.125f;    // 1/sqrt(64)

    float4 q4[16];
    const float4* qp = (const float4*)(qkv + (size_t)(b*SS + qg) * RS + h * HDIM);
    #pragma unroll
    for (int i = 0; i < 16; i++) {
        float4 v = qp[i];
        v.x *= scale; v.y *= scale; v.z *= scale; v.w *= scale;
        q4[i] = v;
    }
    float4 a4[16];
    #pragma unroll
    for (int i = 0; i < 16; i++) a4[i] = make_float4(0.f, 0.f, 0.f, 0.f);
    float m = -INFINITY, l = 0.f;

    __shared__ float4 Ks[32*16];
    __shared__ float4 Vs[32*16];

    int ntiles = qt * 2 + 2;
    for (int kt = 0; kt < ntiles; kt++) {
        __syncthreads();
        for (int u = tid; u < 512; u += 64) {
            int r = u >> 4, c = u & 15;
            size_t base = (size_t)(b*SS + kt*32 + r) * RS + h * HDIM + c * 4;
            Ks[u] = *(const float4*)(qkv + DD   + base);
            Vs[u] = *(const float4*)(qkv + 2*DD + base);
        }
        __syncthreads();

        float sc[32];
        float tmax = -INFINITY;
        int kbase = kt * 32;
        #pragma unroll 4
        for (int j = 0; j < 32; j++) {
            if (kbase + j <= qg) {
                float s = 0.f;
                #pragma unroll
                for (int i = 0; i < 16; i++) {
                    float4 k4 = Ks[j*16 + i];
                    s += q4[i].x*k4.x + q4[i].y*k4.y + q4[i].z*k4.z + q4[i].w*k4.w;
                }
                sc[j] = s;
                tmax = fmaxf(tmax, s);
            } else sc[j] = -INFINITY;
        }
        float mn = fmaxf(m, tmax);
        float corr = expf(m - mn);      // m=-inf, mn finite -> 0
        l *= corr;
        #pragma unroll
        for (int i = 0; i < 16; i++) {
            a4[i].x *= corr; a4[i].y *= corr; a4[i].z *= corr; a4[i].w *= corr;
        }
        for (int j = 0; j < 32; j++) {
            float p = expf(sc[j] - mn);
            l += p;
            #pragma unroll
            for (int i = 0; i < 16; i++) {
                float4 v4 = Vs[j*16 + i];
                a4[i].x += p * v4.x; a4[i].y += p * v4.y;
                a4[i].z += p * v4.z; a4[i].w += p * v4.w;
            }
        }
        m = mn;
    }
    float inv = 1.f / l;
    float4* op = (float4*)(out + (size_t)(b*SS + qg) * DD + h * HDIM);
    #pragma unroll
    for (int i = 0; i < 16; i++) {
        float4 v = a4[i];
        v.x *= inv; v.y *= inv; v.z *= inv; v.w *= inv;
        op[i] = v;
    }
}

// ---------------- router: softmax over 8 experts + top-2 (jax tie-breaks) ------
__global__ void router_k(const float* __restrict__ xn, const float* __restrict__ wr,
                         int* __restrict__ fe, float* __restrict__ fg) {
    int t = blockIdx.x;
    int lane = threadIdx.x & 31, w = threadIdx.x >> 5;   // 8 warps, warp per expert
    const float* xr = xn + (size_t)t * DD;
    float p = 0.f;
    for (int d = lane; d < DD; d += 32) p += xr[d] * wr[(size_t)d * NE + w];
    #pragma unroll
    for (int o = 16; o > 0; o >>= 1) p += __shfl_xor_sync(0xffffffff, p, o);
    __shared__ float lg[NE];
    if (lane == 0) lg[w] = p;
    __syncthreads();
    if (threadIdx.x == 0) {
        float mx = lg[0];
        for (int e = 1; e < NE; e++) mx = fmaxf(mx, lg[e]);
        float pr[NE], sum = 0.f;
        for (int e = 0; e < NE; e++) { pr[e] = expf(lg[e] - mx); sum += pr[e]; }
        float inv = 1.f / sum;
        int e1 = 0; float v1 = pr[0];
        for (int e = 1; e < NE; e++) if (pr[e] > v1) { v1 = pr[e]; e1 = e; }
        int e2 = -1; float v2 = -INFINITY;
        for (int e = 0; e < NE; e++) {
            if (e == e1) continue;
            if (pr[e] > v2) { v2 = pr[e]; e2 = e; }
        }
        fe[2*t]   = e1; fg[2*t]   = v1 * inv;
        fe[2*t+1] = e2; fg[2*t+1] = v2 * inv;
    }
}

__global__ void zero_k(int* cnt) { if (threadIdx.x < NE) cnt[threadIdx.x] = 0; }

__global__ void assign_k(const int* __restrict__ fe, const float* __restrict__ fg,
                         int* __restrict__ cnt, int* __restrict__ esl,
                         float* __restrict__ egt) {
    int s = blockIdx.x * blockDim.x + threadIdx.x;
    if (s >= NS) return;
    int e = fe[s];
    int p = atomicAdd(&cnt[e], 1);
    esl[e*NS + p] = s;
    egt[e*NS + p] = fg[s];
}

// rank-based capacity selection: exactly matches top_k(masked, CAP) semantics,
// deterministic regardless of atomic fill order.
__global__ void select_k(const int* __restrict__ cnt, const int* __restrict__ esl,
                         const float* __restrict__ egt, int* __restrict__ dtok,
                         int* __restrict__ srow) {
    int e = blockIdx.x;
    int n = cnt[e];
    const int*   sl = esl + e*NS;
    const float* gt = egt + e*NS;
    for (int i = threadIdx.x; i < n; i += blockDim.x) {
        float gi = gt[i]; int si = sl[i];
        int rank = 0;
        for (int j = 0; j < n; j++) {
            float gj = gt[j]; int sj = sl[j];
            rank += (gj > gi) || (gj == gi && sj < si);
        }
        if (rank < CAPN) {
            dtok[e*CAPN + rank] = si >> 1;
            srow[si] = e*CAPN + rank;
        } else srow[si] = -1;
    }
    for (int r = n + threadIdx.x; r < CAPN; r += blockDim.x) dtok[e*CAPN + r] = 0;
}

__global__ void gather_k(const int* __restrict__ dtok, const float* __restrict__ xn2,
                         float* __restrict__ xe) {
    int R = blockIdx.x;
    int tok = dtok[R];
    ((float4*)(xe + (size_t)R * DD))[threadIdx.x] =
        ((const float4*)(xn2 + (size_t)tok * DD))[threadIdx.x];
}

__global__ void combine_k(const float* __restrict__ x1, const float* __restrict__ ye,
                          const int* __restrict__ srow, const float* __restrict__ fg,
                          float* __restrict__ out) {
    int t = blockIdx.x;
    float4 o = ((const float4*)(x1 + (size_t)t * DD))[threadIdx.x];
    #pragma unroll
    for (int k = 0; k < 2; k++) {
        int s = 2*t + k;
        int r = srow[s];
        if (r >= 0) {
            float gg = fg[s];
            float4 y = ((const float4*)(ye + (size_t)r * DD))[threadIdx.x];
            o.x += gg*y.x; o.y += gg*y.y; o.z += gg*y.z; o.w += gg*y.w;
        }
    }
    ((float4*)(out + (size_t)t * DD))[threadIdx.x] = o;
}

// ---------------- host ----------------
extern "C" void kernel_launch(void* const* d_in, const int* in_sizes, int n_in,
                              void* d_out, int out_size) {
    const float* x        = (const float*)d_in[0];
    const float* g1       = (const float*)d_in[1];
    const float* w_qkv    = (const float*)d_in[2];
    const float* w_o      = (const float*)d_in[3];
    const float* g2       = (const float*)d_in[4];
    const float* w_router = (const float*)d_in[5];
    const float* w1       = (const float*)d_in[6];
    const float* w2       = (const float*)d_in[7];
    float* out = (float*)d_out;

    float *xn, *qkv, *attn, *x1, *xn2, *fg, *egt, *xe, *h, *ye;
    int *fe, *cnt, *esl, *dtok, *srow;
    cudaGetSymbolAddress((void**)&xn,   g_xn);
    cudaGetSymbolAddress((void**)&qkv,  g_qkv);
    cudaGetSymbolAddress((void**)&attn, g_attn);
    cudaGetSymbolAddress((void**)&x1,   g_x1);
    cudaGetSymbolAddress((void**)&xn2,  g_xn2);
    cudaGetSymbolAddress((void**)&fe,   g_fe);
    cudaGetSymbolAddress((void**)&fg,   g_fg);
    cudaGetSymbolAddress((void**)&cnt,  g_cnt);
    cudaGetSymbolAddress((void**)&esl,  g_esl);
    cudaGetSymbolAddress((void**)&egt,  g_egt);
    cudaGetSymbolAddress((void**)&dtok, g_dtok);
    cudaGetSymbolAddress((void**)&srow, g_srow);
    cudaGetSymbolAddress((void**)&xe,   g_xe);
    cudaGetSymbolAddress((void**)&h,    g_h);
    cudaGetSymbolAddress((void**)&ye,   g_ye);

    // attention branch
    rmsnorm_k<<<TT, 256>>>(x, g1, xn);
    gemm_k<<<dim3(3*DD/64, TT/64, 1), 256>>>(xn, w_qkv, qkv, nullptr,
                                             TT, 3*DD, DD, 0, 0, 0, 0);
    rope_k<<<TT, 256>>>(qkv);
    attn_k<<<dim3(SS/64, BB*HH), 64>>>(qkv, attn);
    gemm_k<<<dim3(DD/64, TT/64, 1), 256>>>(attn, w_o, x1, x,
                                           TT, DD, DD, 0, 0, 0, 0);

    // MoE branch
    rmsnorm_k<<<TT, 256>>>(x1, g2, xn2);
    router_k<<<TT, 256>>>(xn2, w_router, fe, fg);
    zero_k<<<1, 32>>>(cnt);
    assign_k<<<NS/256, 256>>>(fe, fg, cnt, esl, egt);
    select_k<<<NE, 256>>>(cnt, esl, egt, dtok, srow);
    gather_k<<<NE*CAPN, 256>>>(dtok, xn2, xe);
    gemm_k<<<dim3(FFND/64, CAPN/64, NE), 256>>>(xe, w1, h, nullptr,
        CAPN, FFND, DD, (long long)CAPN*DD, (long long)DD*FFND, (long long)CAPN*FFND, 1);
    gemm_k<<<dim3(DD/64, CAPN/64, NE), 256>>>(h, w2, ye, nullptr,
        CAPN, DD, FFND, (long long)CAPN*FFND, (long long)FFND*DD, (long long)CAPN*DD, 0);
    combine_k<<<TT, 256>>>(x1, ye, srow, fg, out);
}

// round 3
// speedup vs baseline: 1.6777x; 1.6777x over previous
#include <cuda_runtime.h>
#include <math.h>
#include <stdint.h>

#define BB   2
#define SS   2048
#define DD   1024
#define HH   16
#define HDIM 64
#define FFND 2048
#define NE   8
#define CAPN 1280
#define TT   (BB*SS)      /* 4096 tokens */
#define NS   (TT*2)       /* 8192 slots  */

// ---------------- scratch (device globals; no allocations) ----------------
__device__ float g_xn  [TT*DD];
__device__ float g_qkv [TT*3*DD];
__device__ float g_attn[TT*DD];
__device__ float g_x1  [TT*DD];
__device__ float g_xn2 [TT*DD];
__device__ int   g_fe  [NS];
__device__ float g_fg  [NS];
__device__ int   g_cnt [NE];
__device__ int   g_esl [NE*NS];
__device__ float g_egt [NE*NS];
__device__ int   g_dtok[NE*CAPN];
__device__ int   g_srow[NS];
__device__ float g_xe  [NE*CAPN*DD];
__device__ float g_h   [NE*CAPN*FFND];
__device__ float g_ye  [NE*CAPN*DD];

// ---------------- rmsnorm: one block per token ----------------
__global__ void rmsnorm_k(const float* __restrict__ in, const float* __restrict__ g,
                          float* __restrict__ out) {
    int t = blockIdx.x;
    const float4* xi = (const float4*)(in + (size_t)t * DD);
    float4 v = xi[threadIdx.x];
    float ss = v.x*v.x + v.y*v.y + v.z*v.z + v.w*v.w;
    __shared__ float red[256];
    red[threadIdx.x] = ss;
    __syncthreads();
    for (int s = 128; s > 0; s >>= 1) {
        if (threadIdx.x < s) red[threadIdx.x] += red[threadIdx.x + s];
        __syncthreads();
    }
    float rms = rsqrtf(red[0] / (float)DD + 1e-6f);
    float4 gv = ((const float4*)g)[threadIdx.x];
    float4 o;
    o.x = v.x * gv.x * rms; o.y = v.y * gv.y * rms;
    o.z = v.z * gv.z * rms; o.w = v.w * gv.w * rms;
    ((float4*)(out + (size_t)t * DD))[threadIdx.x] = o;
}

// ---------------- tf32 tensor-core GEMM: 128x128x16 tiles, double-buffered -----
__device__ __forceinline__ uint32_t f2tf32(float x) {
    uint32_t y;
    asm("cvt.rna.tf32.f32 %0, %1;" : "=r"(y) : "f"(x));
    return y;
}

__device__ __forceinline__ void mma_tf32(float* d, const uint32_t* a, const uint32_t* b) {
    asm volatile(
        "mma.sync.aligned.m16n8k8.row.col.f32.tf32.tf32.f32 "
        "{%0,%1,%2,%3},{%4,%5,%6,%7},{%8,%9},{%0,%1,%2,%3};\n"
        : "+f"(d[0]), "+f"(d[1]), "+f"(d[2]), "+f"(d[3])
        : "r"(a[0]), "r"(a[1]), "r"(a[2]), "r"(a[3]), "r"(b[0]), "r"(b[1]));
}

#define GBM 128
#define GBN 128
#define GBK 16
#define GPAD 4

__global__ __launch_bounds__(256) void gemm_tf32(
    const float* __restrict__ A, const float* __restrict__ B, float* __restrict__ C,
    const float* __restrict__ addend, int M, int N, int K,
    long long sA, long long sB, long long sC, int relu)
{
    int e = blockIdx.z;
    A += (size_t)e * sA; B += (size_t)e * sB; C += (size_t)e * sC;

    __shared__ uint32_t As[2][GBK][GBM + GPAD];
    __shared__ uint32_t Bs[2][GBK][GBN + GPAD];

    int tid  = threadIdx.x;
    int warp = tid >> 5, lane = tid & 31;
    int wm = (warp >> 1) * 32;       // 0,32,64,96
    int wn = (warp & 1) * 64;        // 0,64
    int r  = lane >> 2, c = lane & 3;

    int rowb = blockIdx.y * GBM, colb = blockIdx.x * GBN;

    // A staging: thread loads row (tid>>1), 8 cols starting (tid&1)*8
    int arow  = tid >> 1;
    int acol0 = (tid & 1) * 8;
    // B staging: thread loads row (tid>>4), 8 cols starting (tid&15)*8
    int brow  = tid >> 4;
    int bcol0 = (tid & 15) * 8;

    float a_st[8], b_st[8];
    float acc[2][8][4];
    #pragma unroll
    for (int mi = 0; mi < 2; mi++)
        #pragma unroll
        for (int ni = 0; ni < 8; ni++)
            #pragma unroll
            for (int q = 0; q < 4; q++) acc[mi][ni][q] = 0.f;

    int nk = K / GBK;

    // prologue: load tile 0 into regs then smem
    {
        const float* Ap = A + (size_t)(rowb + arow) * K + acol0;
        *(float4*)&a_st[0] = *(const float4*)(Ap);
        *(float4*)&a_st[4] = *(const float4*)(Ap + 4);
        const float* Bp = B + (size_t)brow * N + colb + bcol0;
        *(float4*)&b_st[0] = *(const float4*)(Bp);
        *(float4*)&b_st[4] = *(const float4*)(Bp + 4);
        #pragma unroll
        for (int i = 0; i < 8; i++) As[0][acol0 + i][arow] = f2tf32(a_st[i]);
        #pragma unroll
        for (int i = 0; i < 8; i++) Bs[0][brow][bcol0 + i] = f2tf32(b_st[i]);
    }
    __syncthreads();

    for (int kt = 0; kt < nk; kt++) {
        int buf = kt & 1;
        if (kt + 1 < nk) {
            const float* Ap = A + (size_t)(rowb + arow) * K + (kt + 1) * GBK + acol0;
            *(float4*)&a_st[0] = *(const float4*)(Ap);
            *(float4*)&a_st[4] = *(const float4*)(Ap + 4);
            const float* Bp = B + (size_t)((kt + 1) * GBK + brow) * N + colb + bcol0;
            *(float4*)&b_st[0] = *(const float4*)(Bp);
            *(float4*)&b_st[4] = *(const float4*)(Bp + 4);
        }
        #pragma unroll
        for (int ks = 0; ks < GBK; ks += 8) {
            uint32_t af[2][4];
            #pragma unroll
            for (int mi = 0; mi < 2; mi++) {
                int m = wm + mi * 16 + r;
                af[mi][0] = As[buf][ks + c][m];
                af[mi][1] = As[buf][ks + c][m + 8];
                af[mi][2] = As[buf][ks + c + 4][m];
                af[mi][3] = As[buf][ks + c + 4][m + 8];
            }
            #pragma unroll
            for (int ni = 0; ni < 8; ni++) {
                uint32_t bf[2];
                int n = wn + ni * 8 + r;
                bf[0] = Bs[buf][ks + c][n];
                bf[1] = Bs[buf][ks + c + 4][n];
                mma_tf32(acc[0][ni], af[0], bf);
                mma_tf32(acc[1][ni], af[1], bf);
            }
        }
        if (kt + 1 < nk) {
            __syncthreads();
            #pragma unroll
            for (int i = 0; i < 8; i++) As[1 - buf][acol0 + i][arow] = f2tf32(a_st[i]);
            #pragma unroll
            for (int i = 0; i < 8; i++) Bs[1 - buf][brow][bcol0 + i] = f2tf32(b_st[i]);
            __syncthreads();
        }
    }

    // epilogue
    #pragma unroll
    for (int mi = 0; mi < 2; mi++) {
        #pragma unroll
        for (int ni = 0; ni < 8; ni++) {
            int row = rowb + wm + mi * 16 + r;
            int col = colb + wn + ni * 8 + 2 * c;
            size_t i0 = (size_t)row * N + col;
            size_t i1 = (size_t)(row + 8) * N + col;
            float2 v0 = make_float2(acc[mi][ni][0], acc[mi][ni][1]);
            float2 v1 = make_float2(acc[mi][ni][2], acc[mi][ni][3]);
            if (addend) {
                float2 d0 = *(const float2*)(addend + i0);
                float2 d1 = *(const float2*)(addend + i1);
                v0.x += d0.x; v0.y += d0.y; v1.x += d1.x; v1.y += d1.y;
            }
            if (relu) {
                v0.x = fmaxf(v0.x, 0.f); v0.y = fmaxf(v0.y, 0.f);
                v1.x = fmaxf(v1.x, 0.f); v1.y = fmaxf(v1.y, 0.f);
            }
            *(float2*)(C + i0) = v0;
            *(float2*)(C + i1) = v1;
        }
    }
}

// ---------------- RoPE in-place on q,k halves of qkv ----------------
__global__ void rope_k(float* __restrict__ qkv) {
    int t = blockIdx.x;
    int s = t % SS;
    for (int w = threadIdx.x; w < 1024; w += blockDim.x) {
        int which = w >> 9;        // 0 = q, 1 = k
        int rem   = w & 511;
        int h     = rem >> 5;
        int i     = rem & 31;
        float theta = exp2f(-(float)i * 0.41524101186092030f);  // 10000^{-i/32}
        float fr = (float)s * theta;
        float cc = cosf(fr), sn = sinf(fr);
        size_t base = (size_t)t * (3*DD) + (size_t)which * DD + h * HDIM + 2*i;
        float xr = qkv[base], xi = qkv[base+1];
        qkv[base]   = xr*cc - xi*sn;
        qkv[base+1] = xr*sn + xi*cc;
    }
}

// ---------------- causal flash attention: 1 query/thread, 128 q per block ----
__global__ __launch_bounds__(128) void attn_k(const float* __restrict__ qkv,
                                              float* __restrict__ out) {
    int qt = blockIdx.x;           // q tile (128 queries)
    int bh = blockIdx.y;
    int b = bh / HH, h = bh % HH;
    int tid = threadIdx.x;
    int qg = qt * 128 + tid;

    const size_t RS = 3 * DD;
    const float scale = 0.125f;    // 1/sqrt(64)

    float4 q4[16];
    const float4* qp = (const float4*)(qkv + (size_t)(b*SS + qg) * RS + h * HDIM);
    #pragma unroll
    for (int i = 0; i < 16; i++) {
        float4 v = qp[i];
        v.x *= scale; v.y *= scale; v.z *= scale; v.w *= scale;
        q4[i] = v;
    }
    float4 a4[16];
    #pragma unroll
    for (int i = 0; i < 16; i++) a4[i] = make_float4(0.f, 0.f, 0.f, 0.f);
    float m = -INFINITY, l = 0.f;

    __shared__ float4 Ks[32*16];
    __shared__ float4 Vs[32*16];

    int ntiles = qt * 4 + 4;
    for (int kt = 0; kt < ntiles; kt++) {
        __syncthreads();
        for (int u = tid; u < 512; u += 128) {
            int rr = u >> 4, cc = u & 15;
            size_t base = (size_t)(b*SS + kt*32 + rr) * RS + h * HDIM + cc * 4;
            Ks[u] = *(const float4*)(qkv + DD   + base);
            Vs[u] = *(const float4*)(qkv + 2*DD + base);
        }
        __syncthreads();

        float sc[32];
        float tmax = -INFINITY;
        int kbase = kt * 32;
        #pragma unroll 4
        for (int j = 0; j < 32; j++) {
            if (kbase + j <= qg) {
                float s = 0.f;
                #pragma unroll
                for (int i = 0; i < 16; i++) {
                    float4 k4 = Ks[j*16 + i];
                    s += q4[i].x*k4.x + q4[i].y*k4.y + q4[i].z*k4.z + q4[i].w*k4.w;
                }
                sc[j] = s;
                tmax = fmaxf(tmax, s);
            } else sc[j] = -INFINITY;
        }
        float mn = fmaxf(m, tmax);
        float corr = __expf(m - mn);
        l *= corr;
        #pragma unroll
        for (int i = 0; i < 16; i++) {
            a4[i].x *= corr; a4[i].y *= corr; a4[i].z *= corr; a4[i].w *= corr;
        }
        for (int j = 0; j < 32; j++) {
            float p = __expf(sc[j] - mn);
            l += p;
            #pragma unroll
            for (int i = 0; i < 16; i++) {
                float4 v4 = Vs[j*16 + i];
                a4[i].x += p * v4.x; a4[i].y += p * v4.y;
                a4[i].z += p * v4.z; a4[i].w += p * v4.w;
            }
        }
        m = mn;
    }
    float inv = 1.f / l;
    float4* op = (float4*)(out + (size_t)(b*SS + qg) * DD + h * HDIM);
    #pragma unroll
    for (int i = 0; i < 16; i++) {
        float4 v = a4[i];
        v.x *= inv; v.y *= inv; v.z *= inv; v.w *= inv;
        op[i] = v;
    }
}

// ---------------- router: softmax over 8 experts + top-2 (jax tie-breaks) ------
__global__ void router_k(const float* __restrict__ xn, const float* __restrict__ wr,
                         int* __restrict__ fe, float* __restrict__ fg) {
    int t = blockIdx.x;
    int lane = threadIdx.x & 31, w = threadIdx.x >> 5;   // 8 warps, warp per expert
    const float* xr = xn + (size_t)t * DD;
    float p = 0.f;
    for (int d = lane; d < DD; d += 32) p += xr[d] * wr[(size_t)d * NE + w];
    #pragma unroll
    for (int o = 16; o > 0; o >>= 1) p += __shfl_xor_sync(0xffffffff, p, o);
    __shared__ float lg[NE];
    if (lane == 0) lg[w] = p;
    __syncthreads();
    if (threadIdx.x == 0) {
        float mx = lg[0];
        for (int e = 1; e < NE; e++) mx = fmaxf(mx, lg[e]);
        float pr[NE], sum = 0.f;
        for (int e = 0; e < NE; e++) { pr[e] = expf(lg[e] - mx); sum += pr[e]; }
        float inv = 1.f / sum;
        int e1 = 0; float v1 = pr[0];
        for (int e = 1; e < NE; e++) if (pr[e] > v1) { v1 = pr[e]; e1 = e; }
        int e2 = -1; float v2 = -INFINITY;
        for (int e = 0; e < NE; e++) {
            if (e == e1) continue;
            if (pr[e] > v2) { v2 = pr[e]; e2 = e; }
        }
        fe[2*t]   = e1; fg[2*t]   = v1 * inv;
        fe[2*t+1] = e2; fg[2*t+1] = v2 * inv;
    }
}

__global__ void zero_k(int* cnt) { if (threadIdx.x < NE) cnt[threadIdx.x] = 0; }

__global__ void assign_k(const int* __restrict__ fe, const float* __restrict__ fg,
                         int* __restrict__ cnt, int* __restrict__ esl,
                         float* __restrict__ egt) {
    int s = blockIdx.x * blockDim.x + threadIdx.x;
    if (s >= NS) return;
    int e = fe[s];
    int p = atomicAdd(&cnt[e], 1);
    esl[e*NS + p] = s;
    egt[e*NS + p] = fg[s];
}

// rank-based capacity selection (deterministic, matches top_k(masked, CAP))
__global__ void select_k(const int* __restrict__ cnt, const int* __restrict__ esl,
                         const float* __restrict__ egt, int* __restrict__ dtok,
                         int* __restrict__ srow) {
    int e = blockIdx.x;
    int n = cnt[e];
    const int*   sl = esl + e*NS;
    const float* gt = egt + e*NS;
    for (int i = threadIdx.x; i < n; i += blockDim.x) {
        float gi = gt[i]; int si = sl[i];
        int rank = 0;
        for (int j = 0; j < n; j++) {
            float gj = gt[j]; int sj = sl[j];
            rank += (gj > gi) || (gj == gi && sj < si);
        }
        if (rank < CAPN) {
            dtok[e*CAPN + rank] = si >> 1;
            srow[si] = e*CAPN + rank;
        } else srow[si] = -1;
    }
    for (int rr = n + threadIdx.x; rr < CAPN; rr += blockDim.x) dtok[e*CAPN + rr] = 0;
}

__global__ void gather_k(const int* __restrict__ dtok, const float* __restrict__ xn2,
                         float* __restrict__ xe) {
    int R = blockIdx.x;
    int tok = dtok[R];
    ((float4*)(xe + (size_t)R * DD))[threadIdx.x] =
        ((const float4*)(xn2 + (size_t)tok * DD))[threadIdx.x];
}

__global__ void combine_k(const float* __restrict__ x1, const float* __restrict__ ye,
                          const int* __restrict__ srow, const float* __restrict__ fg,
                          float* __restrict__ out) {
    int t = blockIdx.x;
    float4 o = ((const float4*)(x1 + (size_t)t * DD))[threadIdx.x];
    #pragma unroll
    for (int k = 0; k < 2; k++) {
        int s = 2*t + k;
        int rr = srow[s];
        if (rr >= 0) {
            float gg = fg[s];
            float4 y = ((const float4*)(ye + (size_t)rr * DD))[threadIdx.x];
            o.x += gg*y.x; o.y += gg*y.y; o.z += gg*y.z; o.w += gg*y.w;
        }
    }
    ((float4*)(out + (size_t)t * DD))[threadIdx.x] = o;
}

// ---------------- host ----------------
extern "C" void kernel_launch(void* const* d_in, const int* in_sizes, int n_in,
                              void* d_out, int out_size) {
    const float* x        = (const float*)d_in[0];
    const float* g1       = (const float*)d_in[1];
    const float* w_qkv    = (const float*)d_in[2];
    const float* w_o      = (const float*)d_in[3];
    const float* g2       = (const float*)d_in[4];
    const float* w_router = (const float*)d_in[5];
    const float* w1       = (const float*)d_in[6];
    const float* w2       = (const float*)d_in[7];
    float* out = (float*)d_out;

    float *xn, *qkv, *attn, *x1, *xn2, *fg, *egt, *xe, *h, *ye;
    int *fe, *cnt, *esl, *dtok, *srow;
    cudaGetSymbolAddress((void**)&xn,   g_xn);
    cudaGetSymbolAddress((void**)&qkv,  g_qkv);
    cudaGetSymbolAddress((void**)&attn, g_attn);
    cudaGetSymbolAddress((void**)&x1,   g_x1);
    cudaGetSymbolAddress((void**)&xn2,  g_xn2);
    cudaGetSymbolAddress((void**)&fe,   g_fe);
    cudaGetSymbolAddress((void**)&fg,   g_fg);
    cudaGetSymbolAddress((void**)&cnt,  g_cnt);
    cudaGetSymbolAddress((void**)&esl,  g_esl);
    cudaGetSymbolAddress((void**)&egt,  g_egt);
    cudaGetSymbolAddress((void**)&dtok, g_dtok);
    cudaGetSymbolAddress((void**)&srow, g_srow);
    cudaGetSymbolAddress((void**)&xe,   g_xe);
    cudaGetSymbolAddress((void**)&h,    g_h);
    cudaGetSymbolAddress((void**)&ye,   g_ye);

    // attention branch
    rmsnorm_k<<<TT, 256>>>(x, g1, xn);
    gemm_tf32<<<dim3(3*DD/GBN, TT/GBM, 1), 256>>>(xn, w_qkv, qkv, nullptr,
                                                  TT, 3*DD, DD, 0, 0, 0, 0);
    rope_k<<<TT, 256>>>(qkv);
    attn_k<<<dim3(SS/128, BB*HH), 128>>>(qkv, attn);
    gemm_tf32<<<dim3(DD/GBN, TT/GBM, 1), 256>>>(attn, w_o, x1, x,
                                                TT, DD, DD, 0, 0, 0, 0);

    // MoE branch
    rmsnorm_k<<<TT, 256>>>(x1, g2, xn2);
    router_k<<<TT, 256>>>(xn2, w_router, fe, fg);
    zero_k<<<1, 32>>>(cnt);
    assign_k<<<NS/256, 256>>>(fe, fg, cnt, esl, egt);
    select_k<<<NE, 256>>>(cnt, esl, egt, dtok, srow);
    gather_k<<<NE*CAPN, 256>>>(dtok, xn2, xe);
    gemm_tf32<<<dim3(FFND/GBN, CAPN/GBM, NE), 256>>>(xe, w1, h, nullptr,
        CAPN, FFND, DD, (long long)CAPN*DD, (long long)DD*FFND, (long long)CAPN*FFND, 1);
    gemm_tf32<<<dim3(DD/GBN, CAPN/GBM, NE), 256>>>(h, w2, ye, nullptr,
        CAPN, DD, FFND, (long long)CAPN*FFND, (long long)FFND*DD, (long long)CAPN*DD, 0);
    combine_k<<<TT, 256>>>(x1, ye, srow, fg, out);
}

// round 4
// speedup vs baseline: 2.2550x; 1.3441x over previous
#include <cuda_runtime.h>
#include <math.h>
#include <stdint.h>

#define BB   2
#define SS   2048
#define DD   1024
#define HH   16
#define HDIM 64
#define FFND 2048
#define NE   8
#define CAPN 1280
#define TT   (BB*SS)
#define NS   (TT*2)

// ---------------- scratch (device globals; no allocations) ----------------
__device__ float g_xn  [TT*DD];
__device__ float g_qkv [TT*3*DD];
__device__ float g_attn[TT*DD];
__device__ float g_x1  [TT*DD];
__device__ float g_xn2 [TT*DD];
__device__ int   g_fe  [NS];
__device__ float g_fg  [NS];
__device__ int   g_cnt [NE];
__device__ int   g_esl [NE*NS];
__device__ float g_egt [NE*NS];
__device__ int   g_dtok[NE*CAPN];
__device__ int   g_srow[NS];
__device__ float g_xe  [NE*CAPN*DD];
__device__ float g_h   [NE*CAPN*FFND];
__device__ float g_ye  [NE*CAPN*DD];

// ---------------- helpers ----------------
__device__ __forceinline__ uint32_t f2tf32(float x) {
    uint32_t y;
    asm("cvt.rna.tf32.f32 %0, %1;" : "=r"(y) : "f"(x));
    return y;
}
__device__ __forceinline__ void mma_tf32(float* d, const uint32_t* a, const uint32_t* b) {
    asm volatile(
        "mma.sync.aligned.m16n8k8.row.col.f32.tf32.tf32.f32 "
        "{%0,%1,%2,%3},{%4,%5,%6,%7},{%8,%9},{%0,%1,%2,%3};\n"
        : "+f"(d[0]), "+f"(d[1]), "+f"(d[2]), "+f"(d[3])
        : "r"(a[0]), "r"(a[1]), "r"(a[2]), "r"(a[3]), "r"(b[0]), "r"(b[1]));
}
// fast exp on FMA pipe (avoids MUFU bottleneck); rel err ~2e-7
__device__ __forceinline__ float fast_exp(float x) {
    float y = fmaxf(x * 1.4426950408889634f, -126.f);
    float n = floorf(y);
    float f = y - n;
    float p =              1.8775767e-3f;
    p = fmaf(p, f, 8.9893397e-3f);
    p = fmaf(p, f, 5.5826318e-2f);
    p = fmaf(p, f, 2.4015361e-1f);
    p = fmaf(p, f, 6.9315308e-1f);
    p = fmaf(p, f, 9.9999994e-1f);
    return __int_as_float(__float_as_int(p) + (((int)n) << 23));
}

// ---------------- rmsnorm ----------------
__global__ void rmsnorm_k(const float* __restrict__ in, const float* __restrict__ g,
                          float* __restrict__ out) {
    int t = blockIdx.x;
    const float4* xi = (const float4*)(in + (size_t)t * DD);
    float4 v = xi[threadIdx.x];
    float ss = v.x*v.x + v.y*v.y + v.z*v.z + v.w*v.w;
    __shared__ float red[256];
    red[threadIdx.x] = ss;
    __syncthreads();
    for (int s = 128; s > 0; s >>= 1) {
        if (threadIdx.x < s) red[threadIdx.x] += red[threadIdx.x + s];
        __syncthreads();
    }
    float rms = rsqrtf(red[0] / (float)DD + 1e-6f);
    float4 gv = ((const float4*)g)[threadIdx.x];
    float4 o;
    o.x = v.x * gv.x * rms; o.y = v.y * gv.y * rms;
    o.z = v.z * gv.z * rms; o.w = v.w * gv.w * rms;
    ((float4*)(out + (size_t)t * DD))[threadIdx.x] = o;
}

// ---------------- tf32 GEMM (unchanged from R2) ----------------
#define GBM 128
#define GBN 128
#define GBK 16
#define GPAD 4

__global__ __launch_bounds__(256) void gemm_tf32(
    const float* __restrict__ A, const float* __restrict__ B, float* __restrict__ C,
    const float* __restrict__ addend, int M, int N, int K,
    long long sA, long long sB, long long sC, int relu)
{
    int e = blockIdx.z;
    A += (size_t)e * sA; B += (size_t)e * sB; C += (size_t)e * sC;

    __shared__ uint32_t As[2][GBK][GBM + GPAD];
    __shared__ uint32_t Bs[2][GBK][GBN + GPAD];

    int tid  = threadIdx.x;
    int warp = tid >> 5, lane = tid & 31;
    int wm = (warp >> 1) * 32;
    int wn = (warp & 1) * 64;
    int r  = lane >> 2, c = lane & 3;

    int rowb = blockIdx.y * GBM, colb = blockIdx.x * GBN;

    int arow  = tid >> 1;
    int acol0 = (tid & 1) * 8;
    int brow  = tid >> 4;
    int bcol0 = (tid & 15) * 8;

    float a_st[8], b_st[8];
    float acc[2][8][4];
    #pragma unroll
    for (int mi = 0; mi < 2; mi++)
        #pragma unroll
        for (int ni = 0; ni < 8; ni++)
            #pragma unroll
            for (int q = 0; q < 4; q++) acc[mi][ni][q] = 0.f;

    int nk = K / GBK;
    {
        const float* Ap = A + (size_t)(rowb + arow) * K + acol0;
        *(float4*)&a_st[0] = *(const float4*)(Ap);
        *(float4*)&a_st[4] = *(const float4*)(Ap + 4);
        const float* Bp = B + (size_t)brow * N + colb + bcol0;
        *(float4*)&b_st[0] = *(const float4*)(Bp);
        *(float4*)&b_st[4] = *(const float4*)(Bp + 4);
        #pragma unroll
        for (int i = 0; i < 8; i++) As[0][acol0 + i][arow] = f2tf32(a_st[i]);
        #pragma unroll
        for (int i = 0; i < 8; i++) Bs[0][brow][bcol0 + i] = f2tf32(b_st[i]);
    }
    __syncthreads();

    for (int kt = 0; kt < nk; kt++) {
        int buf = kt & 1;
        if (kt + 1 < nk) {
            const float* Ap = A + (size_t)(rowb + arow) * K + (kt + 1) * GBK + acol0;
            *(float4*)&a_st[0] = *(const float4*)(Ap);
            *(float4*)&a_st[4] = *(const float4*)(Ap + 4);
            const float* Bp = B + (size_t)((kt + 1) * GBK + brow) * N + colb + bcol0;
            *(float4*)&b_st[0] = *(const float4*)(Bp);
            *(float4*)&b_st[4] = *(const float4*)(Bp + 4);
        }
        #pragma unroll
        for (int ks = 0; ks < GBK; ks += 8) {
            uint32_t af[2][4];
            #pragma unroll
            for (int mi = 0; mi < 2; mi++) {
                int m = wm + mi * 16 + r;
                af[mi][0] = As[buf][ks + c][m];
                af[mi][1] = As[buf][ks + c][m + 8];
                af[mi][2] = As[buf][ks + c + 4][m];
                af[mi][3] = As[buf][ks + c + 4][m + 8];
            }
            #pragma unroll
            for (int ni = 0; ni < 8; ni++) {
                uint32_t bf[2];
                int n = wn + ni * 8 + r;
                bf[0] = Bs[buf][ks + c][n];
                bf[1] = Bs[buf][ks + c + 4][n];
                mma_tf32(acc[0][ni], af[0], bf);
                mma_tf32(acc[1][ni], af[1], bf);
            }
        }
        if (kt + 1 < nk) {
            __syncthreads();
            #pragma unroll
            for (int i = 0; i < 8; i++) As[1 - buf][acol0 + i][arow] = f2tf32(a_st[i]);
            #pragma unroll
            for (int i = 0; i < 8; i++) Bs[1 - buf][brow][bcol0 + i] = f2tf32(b_st[i]);
            __syncthreads();
        }
    }

    #pragma unroll
    for (int mi = 0; mi < 2; mi++) {
        #pragma unroll
        for (int ni = 0; ni < 8; ni++) {
            int row = rowb + wm + mi * 16 + r;
            int col = colb + wn + ni * 8 + 2 * c;
            size_t i0 = (size_t)row * N + col;
            size_t i1 = (size_t)(row + 8) * N + col;
            float2 v0 = make_float2(acc[mi][ni][0], acc[mi][ni][1]);
            float2 v1 = make_float2(acc[mi][ni][2], acc[mi][ni][3]);
            if (addend) {
                float2 d0 = *(const float2*)(addend + i0);
                float2 d1 = *(const float2*)(addend + i1);
                v0.x += d0.x; v0.y += d0.y; v1.x += d1.x; v1.y += d1.y;
            }
            if (relu) {
                v0.x = fmaxf(v0.x, 0.f); v0.y = fmaxf(v0.y, 0.f);
                v1.x = fmaxf(v1.x, 0.f); v1.y = fmaxf(v1.y, 0.f);
            }
            *(float2*)(C + i0) = v0;
            *(float2*)(C + i1) = v1;
        }
    }
}

// ---------------- RoPE in-place on q,k halves of qkv ----------------
__global__ void rope_k(float* __restrict__ qkv) {
    int t = blockIdx.x;
    int s = t % SS;
    for (int w = threadIdx.x; w < 1024; w += blockDim.x) {
        int which = w >> 9;
        int rem   = w & 511;
        int h     = rem >> 5;
        int i     = rem & 31;
        float theta = exp2f(-(float)i * 0.41524101186092030f);
        float fr = (float)s * theta;
        float cc = cosf(fr), sn = sinf(fr);
        size_t base = (size_t)t * (3*DD) + (size_t)which * DD + h * HDIM + 2*i;
        float xr = qkv[base], xi = qkv[base+1];
        qkv[base]   = xr*cc - xi*sn;
        qkv[base+1] = xr*sn + xi*cc;
    }
}

// ---------------- tensor-core flash attention --------------------------
// 64 queries/block (4 warps x 16 rows), 64-key tiles, tf32 mma.
// dyn smem: Qs[64 dims][68 rows] (reused as per-warp Ps[64 keys][17 rows]),
//           Ks[64 keys][68 dims], Vs[64 keys][68 dims]  (all tf32 bits)
#define AT_SMEM (3 * 4352 * 4)

__global__ __launch_bounds__(128) void attn_tc(const float* __restrict__ qkv,
                                               float* __restrict__ out) {
    extern __shared__ uint32_t sm[];
    uint32_t* Qs = sm;            // 64*68 = 4352
    uint32_t* Ks = sm + 4352;
    uint32_t* Vs = sm + 8704;

    int qt = blockIdx.x;
    int bh = blockIdx.y;
    int b = bh >> 4, h = bh & 15;
    int tid = threadIdx.x, warp = tid >> 5, lane = tid & 31;
    int r = lane >> 2, c = lane & 3;
    int qb = qt * 64;
    const size_t RS = 3 * DD;
    const float scale = 0.125f;

    // ---- stage Q tile transposed: Qs[dim][row], scaled, tf32 ----
    for (int u = tid; u < 1024; u += 128) {
        int row = u >> 4, d4 = (u & 15) * 4;
        float4 v = *(const float4*)(qkv + (size_t)(b*SS + qb + row) * RS + h*HDIM + d4);
        Qs[(d4+0)*68 + row] = f2tf32(v.x * scale);
        Qs[(d4+1)*68 + row] = f2tf32(v.y * scale);
        Qs[(d4+2)*68 + row] = f2tf32(v.z * scale);
        Qs[(d4+3)*68 + row] = f2tf32(v.w * scale);
    }
    __syncthreads();

    // ---- Q fragments (loop-invariant) ----
    int mb = warp * 16;
    uint32_t qf[8][4];
    #pragma unroll
    for (int ks = 0; ks < 8; ks++) {
        int k0 = ks * 8;
        qf[ks][0] = Qs[(k0 + c    )*68 + mb + r];
        qf[ks][1] = Qs[(k0 + c    )*68 + mb + r + 8];
        qf[ks][2] = Qs[(k0 + c + 4)*68 + mb + r];
        qf[ks][3] = Qs[(k0 + c + 4)*68 + mb + r + 8];
    }

    uint32_t* Ps = Qs + warp * 1088;   // per-warp [64 keys][17]

    float oacc[8][4];
    #pragma unroll
    for (int ni = 0; ni < 8; ni++)
        #pragma unroll
        for (int q = 0; q < 4; q++) oacc[ni][q] = 0.f;
    float m0 = -INFINITY, m1 = -INFINITY, l0 = 0.f, l1 = 0.f;

    int row0 = qb + mb + r, row1 = row0 + 8;

    for (int kt = 0; kt <= qt; kt++) {
        __syncthreads();           // previous tile's PV done; Q frags extracted
        // ---- stage K, V tiles (tf32) ----
        for (int u = tid; u < 1024; u += 128) {
            int row = u >> 4, d4 = (u & 15) * 4;
            size_t base = (size_t)(b*SS + kt*64 + row) * RS + h*HDIM + d4;
            float4 kv = *(const float4*)(qkv + DD + base);
            Ks[row*68 + d4 + 0] = f2tf32(kv.x);
            Ks[row*68 + d4 + 1] = f2tf32(kv.y);
            Ks[row*68 + d4 + 2] = f2tf32(kv.z);
            Ks[row*68 + d4 + 3] = f2tf32(kv.w);
            float4 vv = *(const float4*)(qkv + 2*DD + base);
            Vs[row*68 + d4 + 0] = f2tf32(vv.x);
            Vs[row*68 + d4 + 1] = f2tf32(vv.y);
            Vs[row*68 + d4 + 2] = f2tf32(vv.z);
            Vs[row*68 + d4 + 3] = f2tf32(vv.w);
        }
        __syncthreads();

        // ---- S = Q K^T ----
        float s[8][4];
        #pragma unroll
        for (int ni = 0; ni < 8; ni++) {
            float sa[4] = {0.f, 0.f, 0.f, 0.f};
            const uint32_t* kr = Ks + (ni*8 + r) * 68;
            #pragma unroll
            for (int ks = 0; ks < 8; ks++) {
                uint32_t bf[2];
                bf[0] = kr[ks*8 + c];
                bf[1] = kr[ks*8 + c + 4];
                mma_tf32(sa, qf[ks], bf);
            }
            s[ni][0] = sa[0]; s[ni][1] = sa[1]; s[ni][2] = sa[2]; s[ni][3] = sa[3];
        }

        // ---- causal mask on diagonal tile ----
        if (kt == qt) {
            #pragma unroll
            for (int ni = 0; ni < 8; ni++) {
                int col = kt*64 + ni*8 + 2*c;
                if (col     > row0) s[ni][0] = -1e30f;
                if (col + 1 > row0) s[ni][1] = -1e30f;
                if (col     > row1) s[ni][2] = -1e30f;
                if (col + 1 > row1) s[ni][3] = -1e30f;
            }
        }

        // ---- online softmax ----
        float mx0 = -1e30f, mx1 = -1e30f;
        #pragma unroll
        for (int ni = 0; ni < 8; ni++) {
            mx0 = fmaxf(mx0, fmaxf(s[ni][0], s[ni][1]));
            mx1 = fmaxf(mx1, fmaxf(s[ni][2], s[ni][3]));
        }
        mx0 = fmaxf(mx0, __shfl_xor_sync(0xffffffff, mx0, 1));
        mx0 = fmaxf(mx0, __shfl_xor_sync(0xffffffff, mx0, 2));
        mx1 = fmaxf(mx1, __shfl_xor_sync(0xffffffff, mx1, 1));
        mx1 = fmaxf(mx1, __shfl_xor_sync(0xffffffff, mx1, 2));
        float mn0 = fmaxf(m0, mx0), mn1 = fmaxf(m1, mx1);
        float cor0 = fast_exp(m0 - mn0), cor1 = fast_exp(m1 - mn1);
        m0 = mn0; m1 = mn1;

        float ls0 = 0.f, ls1 = 0.f;
        #pragma unroll
        for (int ni = 0; ni < 8; ni++) {
            float p0 = fast_exp(s[ni][0] - mn0);
            float p1 = fast_exp(s[ni][1] - mn0);
            float p2 = fast_exp(s[ni][2] - mn1);
            float p3 = fast_exp(s[ni][3] - mn1);
            ls0 += p0 + p1; ls1 += p2 + p3;
            int kc = ni*8 + 2*c;
            Ps[(kc    )*17 + r    ] = f2tf32(p0);
            Ps[(kc + 1)*17 + r    ] = f2tf32(p1);
            Ps[(kc    )*17 + r + 8] = f2tf32(p2);
            Ps[(kc + 1)*17 + r + 8] = f2tf32(p3);
        }
        ls0 += __shfl_xor_sync(0xffffffff, ls0, 1);
        ls0 += __shfl_xor_sync(0xffffffff, ls0, 2);
        ls1 += __shfl_xor_sync(0xffffffff, ls1, 1);
        ls1 += __shfl_xor_sync(0xffffffff, ls1, 2);
        l0 = l0 * cor0 + ls0;
        l1 = l1 * cor1 + ls1;

        #pragma unroll
        for (int ni = 0; ni < 8; ni++) {
            oacc[ni][0] *= cor0; oacc[ni][1] *= cor0;
            oacc[ni][2] *= cor1; oacc[ni][3] *= cor1;
        }
        __syncwarp();

        // ---- O += P V ----
        #pragma unroll
        for (int ks = 0; ks < 8; ks++) {
            int k0 = ks * 8;
            uint32_t af[4];
            af[0] = Ps[(k0 + c    )*17 + r];
            af[1] = Ps[(k0 + c    )*17 + r + 8];
            af[2] = Ps[(k0 + c + 4)*17 + r];
            af[3] = Ps[(k0 + c + 4)*17 + r + 8];
            #pragma unroll
            for (int ni = 0; ni < 8; ni++) {
                uint32_t bf[2];
                bf[0] = Vs[(k0 + c    )*68 + ni*8 + r];
                bf[1] = Vs[(k0 + c + 4)*68 + ni*8 + r];
                mma_tf32(oacc[ni], af, bf);
            }
        }
        __syncwarp();
    }

    // ---- normalize + write ----
    float inv0 = 1.f / l0, inv1 = 1.f / l1;
    #pragma unroll
    for (int ni = 0; ni < 8; ni++) {
        int col = h*HDIM + ni*8 + 2*c;
        *(float2*)(out + (size_t)(b*SS + row0) * DD + col) =
            make_float2(oacc[ni][0]*inv0, oacc[ni][1]*inv0);
        *(float2*)(out + (size_t)(b*SS + row1) * DD + col) =
            make_float2(oacc[ni][2]*inv1, oacc[ni][3]*inv1);
    }
}

// ---------------- router ----------------
__global__ void router_k(const float* __restrict__ xn, const float* __restrict__ wr,
                         int* __restrict__ fe, float* __restrict__ fg) {
    int t = blockIdx.x;
    int lane = threadIdx.x & 31, w = threadIdx.x >> 5;
    const float* xr = xn + (size_t)t * DD;
    float p = 0.f;
    for (int d = lane; d < DD; d += 32) p += xr[d] * wr[(size_t)d * NE + w];
    #pragma unroll
    for (int o = 16; o > 0; o >>= 1) p += __shfl_xor_sync(0xffffffff, p, o);
    __shared__ float lg[NE];
    if (lane == 0) lg[w] = p;
    __syncthreads();
    if (threadIdx.x == 0) {
        float mx = lg[0];
        for (int e = 1; e < NE; e++) mx = fmaxf(mx, lg[e]);
        float pr[NE], sum = 0.f;
        for (int e = 0; e < NE; e++) { pr[e] = expf(lg[e] - mx); sum += pr[e]; }
        float inv = 1.f / sum;
        int e1 = 0; float v1 = pr[0];
        for (int e = 1; e < NE; e++) if (pr[e] > v1) { v1 = pr[e]; e1 = e; }
        int e2 = -1; float v2 = -INFINITY;
        for (int e = 0; e < NE; e++) {
            if (e == e1) continue;
            if (pr[e] > v2) { v2 = pr[e]; e2 = e; }
        }
        fe[2*t]   = e1; fg[2*t]   = v1 * inv;
        fe[2*t+1] = e2; fg[2*t+1] = v2 * inv;
    }
}

__global__ void zero_k(int* cnt) { if (threadIdx.x < NE) cnt[threadIdx.x] = 0; }

__global__ void assign_k(const int* __restrict__ fe, const float* __restrict__ fg,
                         int* __restrict__ cnt, int* __restrict__ esl,
                         float* __restrict__ egt) {
    int s = blockIdx.x * blockDim.x + threadIdx.x;
    if (s >= NS) return;
    int e = fe[s];
    int p = atomicAdd(&cnt[e], 1);
    esl[e*NS + p] = s;
    egt[e*NS + p] = fg[s];
}

__global__ void select_k(const int* __restrict__ cnt, const int* __restrict__ esl,
                         const float* __restrict__ egt, int* __restrict__ dtok,
                         int* __restrict__ srow) {
    int e = blockIdx.x;
    int n = cnt[e];
    const int*   sl = esl + e*NS;
    const float* gt = egt + e*NS;
    for (int i = threadIdx.x; i < n; i += blockDim.x) {
        float gi = gt[i]; int si = sl[i];
        int rank = 0;
        for (int j = 0; j < n; j++) {
            float gj = gt[j]; int sj = sl[j];
            rank += (gj > gi) || (gj == gi && sj < si);
        }
        if (rank < CAPN) {
            dtok[e*CAPN + rank] = si >> 1;
            srow[si] = e*CAPN + rank;
        } else srow[si] = -1;
    }
    for (int rr = n + threadIdx.x; rr < CAPN; rr += blockDim.x) dtok[e*CAPN + rr] = 0;
}

__global__ void gather_k(const int* __restrict__ dtok, const float* __restrict__ xn2,
                         float* __restrict__ xe) {
    int R = blockIdx.x;
    int tok = dtok[R];
    ((float4*)(xe + (size_t)R * DD))[threadIdx.x] =
        ((const float4*)(xn2 + (size_t)tok * DD))[threadIdx.x];
}

__global__ void combine_k(const float* __restrict__ x1, const float* __restrict__ ye,
                          const int* __restrict__ srow, const float* __restrict__ fg,
                          float* __restrict__ out) {
    int t = blockIdx.x;
    float4 o = ((const float4*)(x1 + (size_t)t * DD))[threadIdx.x];
    #pragma unroll
    for (int k = 0; k < 2; k++) {
        int s = 2*t + k;
        int rr = srow[s];
        if (rr >= 0) {
            float gg = fg[s];
            float4 y = ((const float4*)(ye + (size_t)rr * DD))[threadIdx.x];
            o.x += gg*y.x; o.y += gg*y.y; o.z += gg*y.z; o.w += gg*y.w;
        }
    }
    ((float4*)(out + (size_t)t * DD))[threadIdx.x] = o;
}

// ---------------- host ----------------
extern "C" void kernel_launch(void* const* d_in, const int* in_sizes, int n_in,
                              void* d_out, int out_size) {
    const float* x        = (const float*)d_in[0];
    const float* g1       = (const float*)d_in[1];
    const float* w_qkv    = (const float*)d_in[2];
    const float* w_o      = (const float*)d_in[3];
    const float* g2       = (const float*)d_in[4];
    const float* w_router = (const float*)d_in[5];
    const float* w1       = (const float*)d_in[6];
    const float* w2       = (const float*)d_in[7];
    float* out = (float*)d_out;

    float *xn, *qkv, *attn, *x1, *xn2, *fg, *egt, *xe, *h, *ye;
    int *fe, *cnt, *esl, *dtok, *srow;
    cudaGetSymbolAddress((void**)&xn,   g_xn);
    cudaGetSymbolAddress((void**)&qkv,  g_qkv);
    cudaGetSymbolAddress((void**)&attn, g_attn);
    cudaGetSymbolAddress((void**)&x1,   g_x1);
    cudaGetSymbolAddress((void**)&xn2,  g_xn2);
    cudaGetSymbolAddress((void**)&fe,   g_fe);
    cudaGetSymbolAddress((void**)&fg,   g_fg);
    cudaGetSymbolAddress((void**)&cnt,  g_cnt);
    cudaGetSymbolAddress((void**)&esl,  g_esl);
    cudaGetSymbolAddress((void**)&egt,  g_egt);
    cudaGetSymbolAddress((void**)&dtok, g_dtok);
    cudaGetSymbolAddress((void**)&srow, g_srow);
    cudaGetSymbolAddress((void**)&xe,   g_xe);
    cudaGetSymbolAddress((void**)&h,    g_h);
    cudaGetSymbolAddress((void**)&ye,   g_ye);

    static bool attr_set = false;
    if (!attr_set) {
        cudaFuncSetAttribute(attn_tc, cudaFuncAttributeMaxDynamicSharedMemorySize, AT_SMEM);
        attr_set = true;
    }

    // attention branch
    rmsnorm_k<<<TT, 256>>>(x, g1, xn);
    gemm_tf32<<<dim3(3*DD/GBN, TT/GBM, 1), 256>>>(xn, w_qkv, qkv, nullptr,
                                                  TT, 3*DD, DD, 0, 0, 0, 0);
    rope_k<<<TT, 256>>>(qkv);
    attn_tc<<<dim3(SS/64, BB*HH), 128, AT_SMEM>>>(qkv, attn);
    gemm_tf32<<<dim3(DD/GBN, TT/GBM, 1), 256>>>(attn, w_o, x1, x,
                                                TT, DD, DD, 0, 0, 0, 0);

    // MoE branch
    rmsnorm_k<<<TT, 256>>>(x1, g2, xn2);
    router_k<<<TT, 256>>>(xn2, w_router, fe, fg);
    zero_k<<<1, 32>>>(cnt);
    assign_k<<<NS/256, 256>>>(fe, fg, cnt, esl, egt);
    select_k<<<NE, 256>>>(cnt, esl, egt, dtok, srow);
    gather_k<<<NE*CAPN, 256>>>(dtok, xn2, xe);
    gemm_tf32<<<dim3(FFND/GBN, CAPN/GBM, NE), 256>>>(xe, w1, h, nullptr,
        CAPN, FFND, DD, (long long)CAPN*DD, (long long)DD*FFND, (long long)CAPN*FFND, 1);
    gemm_tf32<<<dim3(DD/GBN, CAPN/GBM, NE), 256>>>(h, w2, ye, nullptr,
        CAPN, DD, FFND, (long long)CAPN*FFND, (long long)FFND*DD, (long long)CAPN*DD, 0);
    combine_k<<<TT, 256>>>(x1, ye, srow, fg, out);
}

// round 5
// speedup vs baseline: 3.1543x; 1.3988x over previous
#include <cuda_runtime.h>
#include <math.h>
#include <stdint.h>

#define BB   2
#define SS   2048
#define DD   1024
#define HH   16
#define HDIM 64
#define FFND 2048
#define NE   8
#define CAPN 1280
#define TT   (BB*SS)
#define NS   (TT*2)

// ---------------- scratch (device globals; no allocations) ----------------
__device__ float g_xn  [TT*DD];
__device__ float g_qkv [TT*3*DD];
__device__ float g_attn[TT*DD];
__device__ float g_x1  [TT*DD];
__device__ float g_xn2 [TT*DD];
__device__ int   g_fe  [NS];
__device__ float g_fg  [NS];
__device__ int   g_cnt [NE];
__device__ int   g_esl [NE*NS];
__device__ float g_egt [NE*NS];
__device__ int   g_dtok[NE*CAPN];
__device__ int   g_srow[NS];
__device__ float g_xe  [NE*CAPN*DD];
__device__ float g_h   [NE*CAPN*FFND];
__device__ float g_ye  [NE*CAPN*DD];

// ---------------- helpers ----------------
__device__ __forceinline__ uint32_t f2tf32(float x) {
    uint32_t y;
    asm("cvt.rna.tf32.f32 %0, %1;" : "=r"(y) : "f"(x));
    return y;
}
__device__ __forceinline__ void mma_tf32(float* d, const uint32_t* a, const uint32_t* b) {
    asm volatile(
        "mma.sync.aligned.m16n8k8.row.col.f32.tf32.tf32.f32 "
        "{%0,%1,%2,%3},{%4,%5,%6,%7},{%8,%9},{%0,%1,%2,%3};\n"
        : "+f"(d[0]), "+f"(d[1]), "+f"(d[2]), "+f"(d[3])
        : "r"(a[0]), "r"(a[1]), "r"(a[2]), "r"(a[3]), "r"(b[0]), "r"(b[1]));
}
__device__ __forceinline__ void cp16(uint32_t s, const void* g) {
    asm volatile("cp.async.cg.shared.global [%0], [%1], 16;\n" :: "r"(s), "l"(g));
}
__device__ __forceinline__ void cp_commit() { asm volatile("cp.async.commit_group;\n"); }
template<int N> __device__ __forceinline__ void cp_wait() {
    asm volatile("cp.async.wait_group %0;\n" :: "n"(N));
}
// fast exp on FMA pipe; rel err ~2e-7
__device__ __forceinline__ float fast_exp(float x) {
    float y = fmaxf(x * 1.4426950408889634f, -126.f);
    float n = floorf(y);
    float f = y - n;
    float p =              1.8775767e-3f;
    p = fmaf(p, f, 8.9893397e-3f);
    p = fmaf(p, f, 5.5826318e-2f);
    p = fmaf(p, f, 2.4015361e-1f);
    p = fmaf(p, f, 6.9315308e-1f);
    p = fmaf(p, f, 9.9999994e-1f);
    return __int_as_float(__float_as_int(p) + (((int)n) << 23));
}

// ---------------- rmsnorm ----------------
__global__ void rmsnorm_k(const float* __restrict__ in, const float* __restrict__ g,
                          float* __restrict__ out) {
    int t = blockIdx.x;
    const float4* xi = (const float4*)(in + (size_t)t * DD);
    float4 v = xi[threadIdx.x];
    float ss = v.x*v.x + v.y*v.y + v.z*v.z + v.w*v.w;
    __shared__ float red[256];
    red[threadIdx.x] = ss;
    __syncthreads();
    for (int s = 128; s > 0; s >>= 1) {
        if (threadIdx.x < s) red[threadIdx.x] += red[threadIdx.x + s];
        __syncthreads();
    }
    float rms = rsqrtf(red[0] / (float)DD + 1e-6f);
    float4 gv = ((const float4*)g)[threadIdx.x];
    float4 o;
    o.x = v.x * gv.x * rms; o.y = v.y * gv.y * rms;
    o.z = v.z * gv.z * rms; o.w = v.w * gv.w * rms;
    ((float4*)(out + (size_t)t * DD))[threadIdx.x] = o;
}

// ---------------- tf32 GEMM: 128x128x16, 4-stage cp.async pipeline -----------
#define GBM 128
#define GBN 128
#define GBK 16
#define ST    4
#define AROW  20                 /* 16 + 4 pad : conflict-free A frag loads */
#define BROW  136                /* 128 + 8 pad: conflict-free B frag loads */
#define AW    (GBM*AROW)         /* 2560 words per A stage */
#define BW    (GBK*BROW)         /* 2176 words per B stage */
#define STW   (AW+BW)            /* 4736 words per stage   */
#define GSMEM (ST*STW*4)         /* 75776 bytes            */

__global__ __launch_bounds__(256) void gemm_tf32(
    const float* __restrict__ A, const float* __restrict__ B, float* __restrict__ C,
    const float* __restrict__ addend, int M, int N, int K,
    long long sA, long long sB, long long sC, int relu)
{
    int e = blockIdx.z;
    A += (size_t)e * sA; B += (size_t)e * sB; C += (size_t)e * sC;

    extern __shared__ float smem[];
    uint32_t smem_base = (uint32_t)__cvta_generic_to_shared(smem);

    int tid  = threadIdx.x;
    int warp = tid >> 5, lane = tid & 31;
    int wm = (warp >> 1) * 32;
    int wn = (warp & 1) * 64;
    int r  = lane >> 2, c = lane & 3;

    int rowb = blockIdx.y * GBM, colb = blockIdx.x * GBN;

    // A copy: 512 float4 per tile -> 2 per thread. row = idx>>2, quad = idx&3
    int a_r0 = tid >> 2,           a_q0 = tid & 3;
    int a_r1 = (tid + 256) >> 2,   a_q1 = tid & 3;
    // B copy: 512 float4 per tile -> 2 per thread. krow = idx>>5, quad = idx&31
    int b_k0 = tid >> 5,           b_q0 = tid & 31;
    int b_k1 = (tid + 256) >> 5,   b_q1 = tid & 31;

    float acc[2][8][4];
    #pragma unroll
    for (int mi = 0; mi < 2; mi++)
        #pragma unroll
        for (int ni = 0; ni < 8; ni++)
            #pragma unroll
            for (int q = 0; q < 4; q++) acc[mi][ni][q] = 0.f;

    int nk = K / GBK;

    // ---- stage issuer ----
    auto issue = [&](int stage, int kt) {
        uint32_t sa = smem_base + stage * (STW * 4);
        uint32_t sb = sa + AW * 4;
        int k0 = kt * GBK;
        cp16(sa + (a_r0*AROW + a_q0*4)*4, A + (size_t)(rowb + a_r0)*K + k0 + a_q0*4);
        cp16(sa + (a_r1*AROW + a_q1*4)*4, A + (size_t)(rowb + a_r1)*K + k0 + a_q1*4);
        cp16(sb + (b_k0*BROW + b_q0*4)*4, B + (size_t)(k0 + b_k0)*N + colb + b_q0*4);
        cp16(sb + (b_k1*BROW + b_q1*4)*4, B + (size_t)(k0 + b_k1)*N + colb + b_q1*4);
    };

    int pre = (nk < ST-1) ? nk : ST-1;
    for (int s = 0; s < pre; s++) { issue(s, s); cp_commit(); }
    for (int s = pre; s < ST-1; s++) cp_commit();   // keep group count consistent

    for (int kt = 0; kt < nk; kt++) {
        cp_wait<ST-2>();
        __syncthreads();

        int stage = kt % ST;
        const uint32_t* As = (const uint32_t*)(smem + stage * STW);
        const uint32_t* Bs = (const uint32_t*)(smem + stage * STW + AW);

        #pragma unroll
        for (int ks = 0; ks < GBK; ks += 8) {
            uint32_t af[2][4];
            #pragma unroll
            for (int mi = 0; mi < 2; mi++) {
                int m = wm + mi * 16 + r;
                af[mi][0] = As[ m      *AROW + ks + c    ];
                af[mi][1] = As[(m + 8)*AROW + ks + c    ];
                af[mi][2] = As[ m      *AROW + ks + c + 4];
                af[mi][3] = As[(m + 8)*AROW + ks + c + 4];
            }
            #pragma unroll
            for (int ni = 0; ni < 8; ni++) {
                uint32_t bf[2];
                int n = wn + ni * 8 + r;
                bf[0] = Bs[(ks + c    )*BROW + n];
                bf[1] = Bs[(ks + c + 4)*BROW + n];
                mma_tf32(acc[0][ni], af[0], bf);
                mma_tf32(acc[1][ni], af[1], bf);
            }
        }
        __syncthreads();
        int nx = kt + ST - 1;
        if (nx < nk) issue(nx % ST, nx);
        cp_commit();
    }

    // epilogue
    #pragma unroll
    for (int mi = 0; mi < 2; mi++) {
        #pragma unroll
        for (int ni = 0; ni < 8; ni++) {
            int row = rowb + wm + mi * 16 + r;
            int col = colb + wn + ni * 8 + 2 * c;
            size_t i0 = (size_t)row * N + col;
            size_t i1 = (size_t)(row + 8) * N + col;
            float2 v0 = make_float2(acc[mi][ni][0], acc[mi][ni][1]);
            float2 v1 = make_float2(acc[mi][ni][2], acc[mi][ni][3]);
            if (addend) {
                float2 d0 = *(const float2*)(addend + i0);
                float2 d1 = *(const float2*)(addend + i1);
                v0.x += d0.x; v0.y += d0.y; v1.x += d1.x; v1.y += d1.y;
            }
            if (relu) {
                v0.x = fmaxf(v0.x, 0.f); v0.y = fmaxf(v0.y, 0.f);
                v1.x = fmaxf(v1.x, 0.f); v1.y = fmaxf(v1.y, 0.f);
            }
            *(float2*)(C + i0) = v0;
            *(float2*)(C + i1) = v1;
        }
    }
}

// ---------------- RoPE in-place on q,k halves of qkv ----------------
__global__ void rope_k(float* __restrict__ qkv) {
    int t = blockIdx.x;
    int s = t % SS;
    for (int w = threadIdx.x; w < 1024; w += blockDim.x) {
        int which = w >> 9;
        int rem   = w & 511;
        int h     = rem >> 5;
        int i     = rem & 31;
        float theta = exp2f(-(float)i * 0.41524101186092030f);
        float fr = (float)s * theta;
        float cc, sn;
        __sincosf(fr, &sn, &cc);
        size_t base = (size_t)t * (3*DD) + (size_t)which * DD + h * HDIM + 2*i;
        float xr = qkv[base], xi = qkv[base+1];
        qkv[base]   = xr*cc - xi*sn;
        qkv[base+1] = xr*sn + xi*cc;
    }
}

// ---------------- tensor-core flash attention (unchanged from R3) -------
#define AT_SMEM (3 * 4352 * 4)

__global__ __launch_bounds__(128) void attn_tc(const float* __restrict__ qkv,
                                               float* __restrict__ out) {
    extern __shared__ uint32_t sm[];
    uint32_t* Qs = sm;
    uint32_t* Ks = sm + 4352;
    uint32_t* Vs = sm + 8704;

    int qt = blockIdx.x;
    int bh = blockIdx.y;
    int b = bh >> 4, h = bh & 15;
    int tid = threadIdx.x, warp = tid >> 5, lane = tid & 31;
    int r = lane >> 2, c = lane & 3;
    int qb = qt * 64;
    const size_t RS = 3 * DD;
    const float scale = 0.125f;

    for (int u = tid; u < 1024; u += 128) {
        int row = u >> 4, d4 = (u & 15) * 4;
        float4 v = *(const float4*)(qkv + (size_t)(b*SS + qb + row) * RS + h*HDIM + d4);
        Qs[(d4+0)*68 + row] = f2tf32(v.x * scale);
        Qs[(d4+1)*68 + row] = f2tf32(v.y * scale);
        Qs[(d4+2)*68 + row] = f2tf32(v.z * scale);
        Qs[(d4+3)*68 + row] = f2tf32(v.w * scale);
    }
    __syncthreads();

    int mb = warp * 16;
    uint32_t qf[8][4];
    #pragma unroll
    for (int ks = 0; ks < 8; ks++) {
        int k0 = ks * 8;
        qf[ks][0] = Qs[(k0 + c    )*68 + mb + r];
        qf[ks][1] = Qs[(k0 + c    )*68 + mb + r + 8];
        qf[ks][2] = Qs[(k0 + c + 4)*68 + mb + r];
        qf[ks][3] = Qs[(k0 + c + 4)*68 + mb + r + 8];
    }

    uint32_t* Ps = Qs + warp * 1088;

    float oacc[8][4];
    #pragma unroll
    for (int ni = 0; ni < 8; ni++)
        #pragma unroll
        for (int q = 0; q < 4; q++) oacc[ni][q] = 0.f;
    float m0 = -INFINITY, m1 = -INFINITY, l0 = 0.f, l1 = 0.f;

    int row0 = qb + mb + r, row1 = row0 + 8;

    for (int kt = 0; kt <= qt; kt++) {
        __syncthreads();
        for (int u = tid; u < 1024; u += 128) {
            int row = u >> 4, d4 = (u & 15) * 4;
            size_t base = (size_t)(b*SS + kt*64 + row) * RS + h*HDIM + d4;
            float4 kv = *(const float4*)(qkv + DD + base);
            Ks[row*68 + d4 + 0] = f2tf32(kv.x);
            Ks[row*68 + d4 + 1] = f2tf32(kv.y);
            Ks[row*68 + d4 + 2] = f2tf32(kv.z);
            Ks[row*68 + d4 + 3] = f2tf32(kv.w);
            float4 vv = *(const float4*)(qkv + 2*DD + base);
            Vs[row*68 + d4 + 0] = f2tf32(vv.x);
            Vs[row*68 + d4 + 1] = f2tf32(vv.y);
            Vs[row*68 + d4 + 2] = f2tf32(vv.z);
            Vs[row*68 + d4 + 3] = f2tf32(vv.w);
        }
        __syncthreads();

        float s[8][4];
        #pragma unroll
        for (int ni = 0; ni < 8; ni++) {
            float sa[4] = {0.f, 0.f, 0.f, 0.f};
            const uint32_t* kr = Ks + (ni*8 + r) * 68;
            #pragma unroll
            for (int ks = 0; ks < 8; ks++) {
                uint32_t bf[2];
                bf[0] = kr[ks*8 + c];
                bf[1] = kr[ks*8 + c + 4];
                mma_tf32(sa, qf[ks], bf);
            }
            s[ni][0] = sa[0]; s[ni][1] = sa[1]; s[ni][2] = sa[2]; s[ni][3] = sa[3];
        }

        if (kt == qt) {
            #pragma unroll
            for (int ni = 0; ni < 8; ni++) {
                int col = kt*64 + ni*8 + 2*c;
                if (col     > row0) s[ni][0] = -1e30f;
                if (col + 1 > row0) s[ni][1] = -1e30f;
                if (col     > row1) s[ni][2] = -1e30f;
                if (col + 1 > row1) s[ni][3] = -1e30f;
            }
        }

        float mx0 = -1e30f, mx1 = -1e30f;
        #pragma unroll
        for (int ni = 0; ni < 8; ni++) {
            mx0 = fmaxf(mx0, fmaxf(s[ni][0], s[ni][1]));
            mx1 = fmaxf(mx1, fmaxf(s[ni][2], s[ni][3]));
        }
        mx0 = fmaxf(mx0, __shfl_xor_sync(0xffffffff, mx0, 1));
        mx0 = fmaxf(mx0, __shfl_xor_sync(0xffffffff, mx0, 2));
        mx1 = fmaxf(mx1, __shfl_xor_sync(0xffffffff, mx1, 1));
        mx1 = fmaxf(mx1, __shfl_xor_sync(0xffffffff, mx1, 2));
        float mn0 = fmaxf(m0, mx0), mn1 = fmaxf(m1, mx1);
        float cor0 = fast_exp(m0 - mn0), cor1 = fast_exp(m1 - mn1);
        m0 = mn0; m1 = mn1;

        float ls0 = 0.f, ls1 = 0.f;
        #pragma unroll
        for (int ni = 0; ni < 8; ni++) {
            float p0 = fast_exp(s[ni][0] - mn0);
            float p1 = fast_exp(s[ni][1] - mn0);
            float p2 = fast_exp(s[ni][2] - mn1);
            float p3 = fast_exp(s[ni][3] - mn1);
            ls0 += p0 + p1; ls1 += p2 + p3;
            int kc = ni*8 + 2*c;
            Ps[(kc    )*17 + r    ] = f2tf32(p0);
            Ps[(kc + 1)*17 + r    ] = f2tf32(p1);
            Ps[(kc    )*17 + r + 8] = f2tf32(p2);
            Ps[(kc + 1)*17 + r + 8] = f2tf32(p3);
        }
        ls0 += __shfl_xor_sync(0xffffffff, ls0, 1);
        ls0 += __shfl_xor_sync(0xffffffff, ls0, 2);
        ls1 += __shfl_xor_sync(0xffffffff, ls1, 1);
        ls1 += __shfl_xor_sync(0xffffffff, ls1, 2);
        l0 = l0 * cor0 + ls0;
        l1 = l1 * cor1 + ls1;

        #pragma unroll
        for (int ni = 0; ni < 8; ni++) {
            oacc[ni][0] *= cor0; oacc[ni][1] *= cor0;
            oacc[ni][2] *= cor1; oacc[ni][3] *= cor1;
        }
        __syncwarp();

        #pragma unroll
        for (int ks = 0; ks < 8; ks++) {
            int k0 = ks * 8;
            uint32_t af[4];
            af[0] = Ps[(k0 + c    )*17 + r];
            af[1] = Ps[(k0 + c    )*17 + r + 8];
            af[2] = Ps[(k0 + c + 4)*17 + r];
            af[3] = Ps[(k0 + c + 4)*17 + r + 8];
            #pragma unroll
            for (int ni = 0; ni < 8; ni++) {
                uint32_t bf[2];
                bf[0] = Vs[(k0 + c    )*68 + ni*8 + r];
                bf[1] = Vs[(k0 + c + 4)*68 + ni*8 + r];
                mma_tf32(oacc[ni], af, bf);
            }
        }
        __syncwarp();
    }

    float inv0 = 1.f / l0, inv1 = 1.f / l1;
    #pragma unroll
    for (int ni = 0; ni < 8; ni++) {
        int col = h*HDIM + ni*8 + 2*c;
        *(float2*)(out + (size_t)(b*SS + row0) * DD + col) =
            make_float2(oacc[ni][0]*inv0, oacc[ni][1]*inv0);
        *(float2*)(out + (size_t)(b*SS + row1) * DD + col) =
            make_float2(oacc[ni][2]*inv1, oacc[ni][3]*inv1);
    }
}

// ---------------- router ----------------
__global__ void router_k(const float* __restrict__ xn, const float* __restrict__ wr,
                         int* __restrict__ fe, float* __restrict__ fg) {
    int t = blockIdx.x;
    int lane = threadIdx.x & 31, w = threadIdx.x >> 5;
    const float* xr = xn + (size_t)t * DD;
    float p = 0.f;
    for (int d = lane; d < DD; d += 32) p += xr[d] * wr[(size_t)d * NE + w];
    #pragma unroll
    for (int o = 16; o > 0; o >>= 1) p += __shfl_xor_sync(0xffffffff, p, o);
    __shared__ float lg[NE];
    if (lane == 0) lg[w] = p;
    __syncthreads();
    if (threadIdx.x == 0) {
        float mx = lg[0];
        for (int e = 1; e < NE; e++) mx = fmaxf(mx, lg[e]);
        float pr[NE], sum = 0.f;
        for (int e = 0; e < NE; e++) { pr[e] = expf(lg[e] - mx); sum += pr[e]; }
        float inv = 1.f / sum;
        int e1 = 0; float v1 = pr[0];
        for (int e = 1; e < NE; e++) if (pr[e] > v1) { v1 = pr[e]; e1 = e; }
        int e2 = -1; float v2 = -INFINITY;
        for (int e = 0; e < NE; e++) {
            if (e == e1) continue;
            if (pr[e] > v2) { v2 = pr[e]; e2 = e; }
        }
        fe[2*t]   = e1; fg[2*t]   = v1 * inv;
        fe[2*t+1] = e2; fg[2*t+1] = v2 * inv;
    }
}

__global__ void zero_k(int* cnt) { if (threadIdx.x < NE) cnt[threadIdx.x] = 0; }

__global__ void assign_k(const int* __restrict__ fe, const float* __restrict__ fg,
                         int* __restrict__ cnt, int* __restrict__ esl,
                         float* __restrict__ egt) {
    int s = blockIdx.x * blockDim.x + threadIdx.x;
    if (s >= NS) return;
    int e = fe[s];
    int p = atomicAdd(&cnt[e], 1);
    esl[e*NS + p] = s;
    egt[e*NS + p] = fg[s];
}

__global__ void select_k(const int* __restrict__ cnt, const int* __restrict__ esl,
                         const float* __restrict__ egt, int* __restrict__ dtok,
                         int* __restrict__ srow) {
    int e = blockIdx.x;
    int n = cnt[e];
    const int*   sl = esl + e*NS;
    const float* gt = egt + e*NS;
    for (int i = threadIdx.x; i < n; i += blockDim.x) {
        float gi = gt[i]; int si = sl[i];
        int rank = 0;
        for (int j = 0; j < n; j++) {
            float gj = gt[j]; int sj = sl[j];
            rank += (gj > gi) || (gj == gi && sj < si);
        }
        if (rank < CAPN) {
            dtok[e*CAPN + rank] = si >> 1;
            srow[si] = e*CAPN + rank;
        } else srow[si] = -1;
    }
    for (int rr = n + threadIdx.x; rr < CAPN; rr += blockDim.x) dtok[e*CAPN + rr] = 0;
}

__global__ void gather_k(const int* __restrict__ dtok, const float* __restrict__ xn2,
                         float* __restrict__ xe) {
    int R = blockIdx.x;
    int tok = dtok[R];
    ((float4*)(xe + (size_t)R * DD))[threadIdx.x] =
        ((const float4*)(xn2 + (size_t)tok * DD))[threadIdx.x];
}

__global__ void combine_k(const float* __restrict__ x1, const float* __restrict__ ye,
                          const int* __restrict__ srow, const float* __restrict__ fg,
                          float* __restrict__ out) {
    int t = blockIdx.x;
    float4 o = ((const float4*)(x1 + (size_t)t * DD))[threadIdx.x];
    #pragma unroll
    for (int k = 0; k < 2; k++) {
        int s = 2*t + k;
        int rr = srow[s];
        if (rr >= 0) {
            float gg = fg[s];
            float4 y = ((const float4*)(ye + (size_t)rr * DD))[threadIdx.x];
            o.x += gg*y.x; o.y += gg*y.y; o.z += gg*y.z; o.w += gg*y.w;
        }
    }
    ((float4*)(out + (size_t)t * DD))[threadIdx.x] = o;
}

// ---------------- host ----------------
extern "C" void kernel_launch(void* const* d_in, const int* in_sizes, int n_in,
                              void* d_out, int out_size) {
    const float* x        = (const float*)d_in[0];
    const float* g1       = (const float*)d_in[1];
    const float* w_qkv    = (const float*)d_in[2];
    const float* w_o      = (const float*)d_in[3];
    const float* g2       = (const float*)d_in[4];
    const float* w_router = (const float*)d_in[5];
    const float* w1       = (const float*)d_in[6];
    const float* w2       = (const float*)d_in[7];
    float* out = (float*)d_out;

    float *xn, *qkv, *attn, *x1, *xn2, *fg, *egt, *xe, *h, *ye;
    int *fe, *cnt, *esl, *dtok, *srow;
    cudaGetSymbolAddress((void**)&xn,   g_xn);
    cudaGetSymbolAddress((void**)&qkv,  g_qkv);
    cudaGetSymbolAddress((void**)&attn, g_attn);
    cudaGetSymbolAddress((void**)&x1,   g_x1);
    cudaGetSymbolAddress((void**)&xn2,  g_xn2);
    cudaGetSymbolAddress((void**)&fe,   g_fe);
    cudaGetSymbolAddress((void**)&fg,   g_fg);
    cudaGetSymbolAddress((void**)&cnt,  g_cnt);
    cudaGetSymbolAddress((void**)&esl,  g_esl);
    cudaGetSymbolAddress((void**)&egt,  g_egt);
    cudaGetSymbolAddress((void**)&dtok, g_dtok);
    cudaGetSymbolAddress((void**)&srow, g_srow);
    cudaGetSymbolAddress((void**)&xe,   g_xe);
    cudaGetSymbolAddress((void**)&h,    g_h);
    cudaGetSymbolAddress((void**)&ye,   g_ye);

    static bool attr_set = false;
    if (!attr_set) {
        cudaFuncSetAttribute(attn_tc,   cudaFuncAttributeMaxDynamicSharedMemorySize, AT_SMEM);
        cudaFuncSetAttribute(gemm_tf32, cudaFuncAttributeMaxDynamicSharedMemorySize, GSMEM);
        attr_set = true;
    }

    // attention branch
    rmsnorm_k<<<TT, 256>>>(x, g1, xn);
    gemm_tf32<<<dim3(3*DD/GBN, TT/GBM, 1), 256, GSMEM>>>(xn, w_qkv, qkv, nullptr,
                                                         TT, 3*DD, DD, 0, 0, 0, 0);
    rope_k<<<TT, 256>>>(qkv);
    attn_tc<<<dim3(SS/64, BB*HH), 128, AT_SMEM>>>(qkv, attn);
    gemm_tf32<<<dim3(DD/GBN, TT/GBM, 1), 256, GSMEM>>>(attn, w_o, x1, x,
                                                       TT, DD, DD, 0, 0, 0, 0);

    // MoE branch
    rmsnorm_k<<<TT, 256>>>(x1, g2, xn2);
    router_k<<<TT, 256>>>(xn2, w_router, fe, fg);
    zero_k<<<1, 32>>>(cnt);
    assign_k<<<NS/256, 256>>>(fe, fg, cnt, esl, egt);
    select_k<<<NE, 256>>>(cnt, esl, egt, dtok, srow);
    gather_k<<<NE*CAPN, 256>>>(dtok, xn2, xe);
    gemm_tf32<<<dim3(FFND/GBN, CAPN/GBM, NE), 256, GSMEM>>>(xe, w1, h, nullptr,
        CAPN, FFND, DD, (long long)CAPN*DD, (long long)DD*FFND, (long long)CAPN*FFND, 1);
    gemm_tf32<<<dim3(DD/GBN, CAPN/GBM, NE), 256, GSMEM>>>(h, w2, ye, nullptr,
        CAPN, DD, FFND, (long long)CAPN*FFND, (long long)FFND*DD, (long long)CAPN*DD, 0);
    combine_k<<<TT, 256>>>(x1, ye, srow, fg, out);
}

// round 7
// speedup vs baseline: 3.2562x; 1.0323x over previous
#include <cuda_runtime.h>
#include <math.h>
#include <stdint.h>

#define BB   2
#define SS   2048
#define DD   1024
#define HH   16
#define HDIM 64
#define FFND 2048
#define NE   8
#define CAPN 1280
#define TT   (BB*SS)
#define NS   (TT*2)

// ---------------- scratch (device globals; no allocations) ----------------
__device__ float g_xn  [TT*DD];
__device__ float g_qkv [TT*3*DD];
__device__ float g_attn[TT*DD];
__device__ float g_x1  [TT*DD];
__device__ float g_xn2 [TT*DD];
__device__ int   g_fe  [NS];
__device__ float g_fg  [NS];
__device__ int   g_cnt [NE];
__device__ int   g_esl [NE*NS];
__device__ float g_egt [NE*NS];
__device__ int   g_dtok[NE*CAPN];
__device__ int   g_srow[NS];
__device__ float g_xe  [NE*CAPN*DD];
__device__ float g_h   [NE*CAPN*FFND];
__device__ float g_ye  [NE*CAPN*DD];

// ---------------- helpers ----------------
__device__ __forceinline__ uint32_t f2tf32(float x) {
    uint32_t y;
    asm("cvt.rna.tf32.f32 %0, %1;" : "=r"(y) : "f"(x));
    return y;
}
__device__ __forceinline__ uint32_t u2tf32(uint32_t x) {
    uint32_t y;
    asm("cvt.rna.tf32.f32 %0, %1;" : "=r"(y) : "r"(x));
    return y;
}
__device__ __forceinline__ void mma_tf32(float* d, const uint32_t* a, const uint32_t* b) {
    asm volatile(
        "mma.sync.aligned.m16n8k8.row.col.f32.tf32.tf32.f32 "
        "{%0,%1,%2,%3},{%4,%5,%6,%7},{%8,%9},{%0,%1,%2,%3};\n"
        : "+f"(d[0]), "+f"(d[1]), "+f"(d[2]), "+f"(d[3])
        : "r"(a[0]), "r"(a[1]), "r"(a[2]), "r"(a[3]), "r"(b[0]), "r"(b[1]));
}
__device__ __forceinline__ void cp16(uint32_t s, const void* g) {
    asm volatile("cp.async.cg.shared.global [%0], [%1], 16;\n" :: "r"(s), "l"(g));
}
__device__ __forceinline__ void cp_commit() { asm volatile("cp.async.commit_group;\n"); }
template<int N> __device__ __forceinline__ void cp_wait() {
    asm volatile("cp.async.wait_group %0;\n" :: "n"(N));
}
// fast exp on FMA pipe; rel err ~2e-7
__device__ __forceinline__ float fast_exp(float x) {
    float y = fmaxf(x * 1.4426950408889634f, -126.f);
    float n = floorf(y);
    float f = y - n;
    float p =              1.8775767e-3f;
    p = fmaf(p, f, 8.9893397e-3f);
    p = fmaf(p, f, 5.5826318e-2f);
    p = fmaf(p, f, 2.4015361e-1f);
    p = fmaf(p, f, 6.9315308e-1f);
    p = fmaf(p, f, 9.9999994e-1f);
    return __int_as_float(__float_as_int(p) + (((int)n) << 23));
}

// ---------------- rmsnorm ----------------
__global__ void rmsnorm_k(const float* __restrict__ in, const float* __restrict__ g,
                          float* __restrict__ out) {
    int t = blockIdx.x;
    const float4* xi = (const float4*)(in + (size_t)t * DD);
    float4 v = xi[threadIdx.x];
    float ss = v.x*v.x + v.y*v.y + v.z*v.z + v.w*v.w;
    __shared__ float red[256];
    red[threadIdx.x] = ss;
    __syncthreads();
    for (int s = 128; s > 0; s >>= 1) {
        if (threadIdx.x < s) red[threadIdx.x] += red[threadIdx.x + s];
        __syncthreads();
    }
    float rms = rsqrtf(red[0] / (float)DD + 1e-6f);
    float4 gv = ((const float4*)g)[threadIdx.x];
    float4 o;
    o.x = v.x * gv.x * rms; o.y = v.y * gv.y * rms;
    o.z = v.z * gv.z * rms; o.w = v.w * gv.w * rms;
    ((float4*)(out + (size_t)t * DD))[threadIdx.x] = o;
}

// ---------------- tf32 GEMM: 128x128x16, 4-stage cp.async, single sync --------
#define GBM 128
#define GBN 128
#define GBK 16
#define ST    4
#define AROW  20
#define BROW  136
#define AW    (GBM*AROW)
#define BW    (GBK*BROW)
#define STW   (AW+BW)
#define GSMEM (ST*STW*4)

__global__ __launch_bounds__(256) void gemm_tf32(
    const float* __restrict__ A, const float* __restrict__ B, float* __restrict__ C,
    const float* __restrict__ addend, int M, int N, int K,
    long long sA, long long sB, long long sC, int relu)
{
    int e = blockIdx.z;
    A += (size_t)e * sA; B += (size_t)e * sB; C += (size_t)e * sC;

    extern __shared__ float smem[];
    uint32_t smem_base = (uint32_t)__cvta_generic_to_shared(smem);

    int tid  = threadIdx.x;
    int warp = tid >> 5, lane = tid & 31;
    int wm = (warp >> 1) * 32;
    int wn = (warp & 1) * 64;
    int r  = lane >> 2, c = lane & 3;

    int rowb = blockIdx.y * GBM, colb = blockIdx.x * GBN;

    int a_r0 = tid >> 2,           a_q0 = tid & 3;
    int a_r1 = (tid + 256) >> 2,   a_q1 = tid & 3;
    int b_k0 = tid >> 5,           b_q0 = tid & 31;
    int b_k1 = (tid + 256) >> 5,   b_q1 = tid & 31;

    float acc[2][8][4];
    #pragma unroll
    for (int mi = 0; mi < 2; mi++)
        #pragma unroll
        for (int ni = 0; ni < 8; ni++)
            #pragma unroll
            for (int q = 0; q < 4; q++) acc[mi][ni][q] = 0.f;

    int nk = K / GBK;

    auto issue = [&](int stage, int kt) {
        uint32_t sa = smem_base + stage * (STW * 4);
        uint32_t sb = sa + AW * 4;
        int k0 = kt * GBK;
        cp16(sa + (a_r0*AROW + a_q0*4)*4, A + (size_t)(rowb + a_r0)*K + k0 + a_q0*4);
        cp16(sa + (a_r1*AROW + a_q1*4)*4, A + (size_t)(rowb + a_r1)*K + k0 + a_q1*4);
        cp16(sb + (b_k0*BROW + b_q0*4)*4, B + (size_t)(k0 + b_k0)*N + colb + b_q0*4);
        cp16(sb + (b_k1*BROW + b_q1*4)*4, B + (size_t)(k0 + b_k1)*N + colb + b_q1*4);
    };

    int pre = (nk < ST-1) ? nk : ST-1;
    for (int s = 0; s < pre; s++) { issue(s, s); cp_commit(); }
    for (int s = pre; s < ST-1; s++) cp_commit();

    for (int kt = 0; kt < nk; kt++) {
        cp_wait<ST-2>();
        __syncthreads();

        int nx = kt + ST - 1;
        if (nx < nk) issue(nx % ST, nx);
        cp_commit();

        int stage = kt % ST;
        const uint32_t* As = (const uint32_t*)(smem + stage * STW);
        const uint32_t* Bs = (const uint32_t*)(smem + stage * STW + AW);

        #pragma unroll
        for (int ks = 0; ks < GBK; ks += 8) {
            uint32_t af[2][4];
            #pragma unroll
            for (int mi = 0; mi < 2; mi++) {
                int m = wm + mi * 16 + r;
                af[mi][0] = As[ m      *AROW + ks + c    ];
                af[mi][1] = As[(m + 8)*AROW + ks + c    ];
                af[mi][2] = As[ m      *AROW + ks + c + 4];
                af[mi][3] = As[(m + 8)*AROW + ks + c + 4];
            }
            #pragma unroll
            for (int ni = 0; ni < 8; ni++) {
                uint32_t bf[2];
                int n = wn + ni * 8 + r;
                bf[0] = Bs[(ks + c    )*BROW + n];
                bf[1] = Bs[(ks + c + 4)*BROW + n];
                mma_tf32(acc[0][ni], af[0], bf);
                mma_tf32(acc[1][ni], af[1], bf);
            }
        }
    }

    #pragma unroll
    for (int mi = 0; mi < 2; mi++) {
        #pragma unroll
        for (int ni = 0; ni < 8; ni++) {
            int row = rowb + wm + mi * 16 + r;
            int col = colb + wn + ni * 8 + 2 * c;
            size_t i0 = (size_t)row * N + col;
            size_t i1 = (size_t)(row + 8) * N + col;
            float2 v0 = make_float2(acc[mi][ni][0], acc[mi][ni][1]);
            float2 v1 = make_float2(acc[mi][ni][2], acc[mi][ni][3]);
            if (addend) {
                float2 d0 = *(const float2*)(addend + i0);
                float2 d1 = *(const float2*)(addend + i1);
                v0.x += d0.x; v0.y += d0.y; v1.x += d1.x; v1.y += d1.y;
            }
            if (relu) {
                v0.x = fmaxf(v0.x, 0.f); v0.y = fmaxf(v0.y, 0.f);
                v1.x = fmaxf(v1.x, 0.f); v1.y = fmaxf(v1.y, 0.f);
            }
            *(float2*)(C + i0) = v0;
            *(float2*)(C + i1) = v1;
        }
    }
}

// ---------------- RoPE in-place on q,k halves of qkv ----------------
__global__ void rope_k(float* __restrict__ qkv) {
    int t = blockIdx.x;
    int s = t % SS;
    for (int w = threadIdx.x; w < 1024; w += blockDim.x) {
        int which = w >> 9;
        int rem   = w & 511;
        int h     = rem >> 5;
        int i     = rem & 31;
        float theta = exp2f(-(float)i * 0.41524101186092030f);
        float fr = (float)s * theta;
        float cc, sn;
        __sincosf(fr, &sn, &cc);
        size_t base = (size_t)t * (3*DD) + (size_t)which * DD + h * HDIM + 2*i;
        float xr = qkv[base], xi = qkv[base+1];
        qkv[base]   = xr*cc - xi*sn;
        qkv[base+1] = xr*sn + xi*cc;
    }
}

// ---------------- tensor-core flash attention, cp.async + rna convert pass ----
// smem words: Qs/Ps 4352 | K0 4352 | K1 4352 | V0 4352 | V1 4352
#define AT_SMEM (5 * 4352 * 4)

__global__ __launch_bounds__(128) void attn_tc(const float* __restrict__ qkv,
                                               float* __restrict__ out) {
    extern __shared__ uint32_t sm[];
    uint32_t* Qs = sm;
    uint32_t smem_base = (uint32_t)__cvta_generic_to_shared(sm);

    int qt = gridDim.x - 1 - blockIdx.x;     // longest blocks first
    int bh = blockIdx.y;
    int b = bh >> 4, h = bh & 15;
    int tid = threadIdx.x, warp = tid >> 5, lane = tid & 31;
    int r = lane >> 2, c = lane & 3;
    int qb = qt * 64;
    const size_t RS = 3 * DD;
    const float scale = 0.125f;

    auto issue = [&](int st, int kt) {
        uint32_t kbase = smem_base + (4352 + st*4352) * 4;
        uint32_t vbase = smem_base + (13056 + st*4352) * 4;
        const float* src = qkv + (size_t)(b*SS + kt*64) * RS + h*HDIM;
        #pragma unroll
        for (int u = tid; u < 1024; u += 128) {
            int row = u >> 4, q = (u & 15) * 4;
            size_t off = (size_t)row * RS + q;
            cp16(kbase + (row*68 + q)*4, src + DD   + off);
            cp16(vbase + (row*68 + q)*4, src + 2*DD + off);
        }
    };
    issue(0, 0);
    cp_commit();

    // ---- stage Q tile transposed (scaled, rna tf32) ----
    for (int u = tid; u < 1024; u += 128) {
        int row = u >> 4, d4 = (u & 15) * 4;
        float4 v = *(const float4*)(qkv + (size_t)(b*SS + qb + row) * RS + h*HDIM + d4);
        Qs[(d4+0)*68 + row] = f2tf32(v.x * scale);
        Qs[(d4+1)*68 + row] = f2tf32(v.y * scale);
        Qs[(d4+2)*68 + row] = f2tf32(v.z * scale);
        Qs[(d4+3)*68 + row] = f2tf32(v.w * scale);
    }
    __syncthreads();

    int mb = warp * 16;
    uint32_t qf[8][4];
    #pragma unroll
    for (int ks = 0; ks < 8; ks++) {
        int k0 = ks * 8;
        qf[ks][0] = Qs[(k0 + c    )*68 + mb + r];
        qf[ks][1] = Qs[(k0 + c    )*68 + mb + r + 8];
        qf[ks][2] = Qs[(k0 + c + 4)*68 + mb + r];
        qf[ks][3] = Qs[(k0 + c + 4)*68 + mb + r + 8];
    }

    uint32_t* Ps = Qs + warp * 1088;

    float oacc[8][4];
    #pragma unroll
    for (int ni = 0; ni < 8; ni++)
        #pragma unroll
        for (int q = 0; q < 4; q++) oacc[ni][q] = 0.f;
    float m0 = -INFINITY, m1 = -INFINITY, l0 = 0.f, l1 = 0.f;

    int row0 = qb + mb + r, row1 = row0 + 8;

    for (int kt = 0; kt <= qt; kt++) {
        __syncthreads();                   // prior compute on overwritten stage done
        if (kt + 1 <= qt) issue((kt + 1) & 1, kt + 1);
        cp_commit();
        cp_wait<1>();
        __syncthreads();                   // tile kt visible

        uint32_t* Kst = sm + 4352  + (kt & 1) * 4352;
        uint32_t* Vst = sm + 13056 + (kt & 1) * 4352;

        // ---- in-place rna fp32->tf32 convert of K/V stage (zero-mean rounding) ----
        #pragma unroll
        for (int u = tid; u < 1024; u += 128) {
            int idx = (u >> 4)*68 + (u & 15)*4;
            uint4 kq = *(uint4*)&Kst[idx];
            kq.x = u2tf32(kq.x); kq.y = u2tf32(kq.y);
            kq.z = u2tf32(kq.z); kq.w = u2tf32(kq.w);
            *(uint4*)&Kst[idx] = kq;
            uint4 vq = *(uint4*)&Vst[idx];
            vq.x = u2tf32(vq.x); vq.y = u2tf32(vq.y);
            vq.z = u2tf32(vq.z); vq.w = u2tf32(vq.w);
            *(uint4*)&Vst[idx] = vq;
        }
        __syncthreads();

        // ---- S = Q K^T ----
        float s[8][4];
        #pragma unroll
        for (int ni = 0; ni < 8; ni++) {
            float sa[4] = {0.f, 0.f, 0.f, 0.f};
            const uint32_t* kr = Kst + (ni*8 + r) * 68;
            #pragma unroll
            for (int ks = 0; ks < 8; ks++) {
                uint32_t bf[2];
                bf[0] = kr[ks*8 + c];
                bf[1] = kr[ks*8 + c + 4];
                mma_tf32(sa, qf[ks], bf);
            }
            s[ni][0] = sa[0]; s[ni][1] = sa[1]; s[ni][2] = sa[2]; s[ni][3] = sa[3];
        }

        if (kt == qt) {
            #pragma unroll
            for (int ni = 0; ni < 8; ni++) {
                int col = kt*64 + ni*8 + 2*c;
                if (col     > row0) s[ni][0] = -1e30f;
                if (col + 1 > row0) s[ni][1] = -1e30f;
                if (col     > row1) s[ni][2] = -1e30f;
                if (col + 1 > row1) s[ni][3] = -1e30f;
            }
        }

        float mx0 = -1e30f, mx1 = -1e30f;
        #pragma unroll
        for (int ni = 0; ni < 8; ni++) {
            mx0 = fmaxf(mx0, fmaxf(s[ni][0], s[ni][1]));
            mx1 = fmaxf(mx1, fmaxf(s[ni][2], s[ni][3]));
        }
        mx0 = fmaxf(mx0, __shfl_xor_sync(0xffffffff, mx0, 1));
        mx0 = fmaxf(mx0, __shfl_xor_sync(0xffffffff, mx0, 2));
        mx1 = fmaxf(mx1, __shfl_xor_sync(0xffffffff, mx1, 1));
        mx1 = fmaxf(mx1, __shfl_xor_sync(0xffffffff, mx1, 2));
        float mn0 = fmaxf(m0, mx0), mn1 = fmaxf(m1, mx1);
        float cor0 = fast_exp(m0 - mn0), cor1 = fast_exp(m1 - mn1);
        m0 = mn0; m1 = mn1;

        float ls0 = 0.f, ls1 = 0.f;
        #pragma unroll
        for (int ni = 0; ni < 8; ni++) {
            float p0 = fast_exp(s[ni][0] - mn0);
            float p1 = fast_exp(s[ni][1] - mn0);
            float p2 = fast_exp(s[ni][2] - mn1);
            float p3 = fast_exp(s[ni][3] - mn1);
            ls0 += p0 + p1; ls1 += p2 + p3;
            int kc = ni*8 + 2*c;
            Ps[(kc    )*17 + r    ] = f2tf32(p0);
            Ps[(kc + 1)*17 + r    ] = f2tf32(p1);
            Ps[(kc    )*17 + r + 8] = f2tf32(p2);
            Ps[(kc + 1)*17 + r + 8] = f2tf32(p3);
        }
        ls0 += __shfl_xor_sync(0xffffffff, ls0, 1);
        ls0 += __shfl_xor_sync(0xffffffff, ls0, 2);
        ls1 += __shfl_xor_sync(0xffffffff, ls1, 1);
        ls1 += __shfl_xor_sync(0xffffffff, ls1, 2);
        l0 = l0 * cor0 + ls0;
        l1 = l1 * cor1 + ls1;

        #pragma unroll
        for (int ni = 0; ni < 8; ni++) {
            oacc[ni][0] *= cor0; oacc[ni][1] *= cor0;
            oacc[ni][2] *= cor1; oacc[ni][3] *= cor1;
        }
        __syncwarp();

        #pragma unroll
        for (int ks = 0; ks < 8; ks++) {
            int k0 = ks * 8;
            uint32_t af[4];
            af[0] = Ps[(k0 + c    )*17 + r];
            af[1] = Ps[(k0 + c    )*17 + r + 8];
            af[2] = Ps[(k0 + c + 4)*17 + r];
            af[3] = Ps[(k0 + c + 4)*17 + r + 8];
            #pragma unroll
            for (int ni = 0; ni < 8; ni++) {
                uint32_t bf[2];
                bf[0] = Vst[(k0 + c    )*68 + ni*8 + r];
                bf[1] = Vst[(k0 + c + 4)*68 + ni*8 + r];
                mma_tf32(oacc[ni], af, bf);
            }
        }
        __syncwarp();
    }

    float inv0 = 1.f / l0, inv1 = 1.f / l1;
    #pragma unroll
    for (int ni = 0; ni < 8; ni++) {
        int col = h*HDIM + ni*8 + 2*c;
        *(float2*)(out + (size_t)(b*SS + row0) * DD + col) =
            make_float2(oacc[ni][0]*inv0, oacc[ni][1]*inv0);
        *(float2*)(out + (size_t)(b*SS + row1) * DD + col) =
            make_float2(oacc[ni][2]*inv1, oacc[ni][3]*inv1);
    }
}

// ---------------- router ----------------
__global__ void router_k(const float* __restrict__ xn, const float* __restrict__ wr,
                         int* __restrict__ fe, float* __restrict__ fg) {
    int t = blockIdx.x;
    int lane = threadIdx.x & 31, w = threadIdx.x >> 5;
    const float* xr = xn + (size_t)t * DD;
    float p = 0.f;
    for (int d = lane; d < DD; d += 32) p += xr[d] * wr[(size_t)d * NE + w];
    #pragma unroll
    for (int o = 16; o > 0; o >>= 1) p += __shfl_xor_sync(0xffffffff, p, o);
    __shared__ float lg[NE];
    if (lane == 0) lg[w] = p;
    __syncthreads();
    if (threadIdx.x == 0) {
        float mx = lg[0];
        for (int e = 1; e < NE; e++) mx = fmaxf(mx, lg[e]);
        float pr[NE], sum = 0.f;
        for (int e = 0; e < NE; e++) { pr[e] = expf(lg[e] - mx); sum += pr[e]; }
        float inv = 1.f / sum;
        int e1 = 0; float v1 = pr[0];
        for (int e = 1; e < NE; e++) if (pr[e] > v1) { v1 = pr[e]; e1 = e; }
        int e2 = -1; float v2 = -INFINITY;
        for (int e = 0; e < NE; e++) {
            if (e == e1) continue;
            if (pr[e] > v2) { v2 = pr[e]; e2 = e; }
        }
        fe[2*t]   = e1; fg[2*t]   = v1 * inv;
        fe[2*t+1] = e2; fg[2*t+1] = v2 * inv;
    }
}

__global__ void zero_k(int* cnt) { if (threadIdx.x < NE) cnt[threadIdx.x] = 0; }

__global__ void assign_k(const int* __restrict__ fe, const float* __restrict__ fg,
                         int* __restrict__ cnt, int* __restrict__ esl,
                         float* __restrict__ egt) {
    int s = blockIdx.x * blockDim.x + threadIdx.x;
    if (s >= NS) return;
    int e = fe[s];
    int p = atomicAdd(&cnt[e], 1);
    esl[e*NS + p] = s;
    egt[e*NS + p] = fg[s];
}

__global__ void select_k(const int* __restrict__ cnt, const int* __restrict__ esl,
                         const float* __restrict__ egt, int* __restrict__ dtok,
                         int* __restrict__ srow) {
    int e = blockIdx.x;
    int n = cnt[e];
    const int*   sl = esl + e*NS;
    const float* gt = egt + e*NS;
    for (int i = threadIdx.x; i < n; i += blockDim.x) {
        float gi = gt[i]; int si = sl[i];
        int rank = 0;
        for (int j = 0; j < n; j++) {
            float gj = gt[j]; int sj = sl[j];
            rank += (gj > gi) || (gj == gi && sj < si);
        }
        if (rank < CAPN) {
            dtok[e*CAPN + rank] = si >> 1;
            srow[si] = e*CAPN + rank;
        } else srow[si] = -1;
    }
    for (int rr = n + threadIdx.x; rr < CAPN; rr += blockDim.x) dtok[e*CAPN + rr] = 0;
}

__global__ void gather_k(const int* __restrict__ dtok, const float* __restrict__ xn2,
                         float* __restrict__ xe) {
    int R = blockIdx.x;
    int tok = dtok[R];
    ((float4*)(xe + (size_t)R * DD))[threadIdx.x] =
        ((const float4*)(xn2 + (size_t)tok * DD))[threadIdx.x];
}

__global__ void combine_k(const float* __restrict__ x1, const float* __restrict__ ye,
                          const int* __restrict__ srow, const float* __restrict__ fg,
                          float* __restrict__ out) {
    int t = blockIdx.x;
    float4 o = ((const float4*)(x1 + (size_t)t * DD))[threadIdx.x];
    #pragma unroll
    for (int k = 0; k < 2; k++) {
        int s = 2*t + k;
        int rr = srow[s];
        if (rr >= 0) {
            float gg = fg[s];
            float4 y = ((const float4*)(ye + (size_t)rr * DD))[threadIdx.x];
            o.x += gg*y.x; o.y += gg*y.y; o.z += gg*y.z; o.w += gg*y.w;
        }
    }
    ((float4*)(out + (size_t)t * DD))[threadIdx.x] = o;
}

// ---------------- host ----------------
extern "C" void kernel_launch(void* const* d_in, const int* in_sizes, int n_in,
                              void* d_out, int out_size) {
    const float* x        = (const float*)d_in[0];
    const float* g1       = (const float*)d_in[1];
    const float* w_qkv    = (const float*)d_in[2];
    const float* w_o      = (const float*)d_in[3];
    const float* g2       = (const float*)d_in[4];
    const float* w_router = (const float*)d_in[5];
    const float* w1       = (const float*)d_in[6];
    const float* w2       = (const float*)d_in[7];
    float* out = (float*)d_out;

    float *xn, *qkv, *attn, *x1, *xn2, *fg, *egt, *xe, *h, *ye;
    int *fe, *cnt, *esl, *dtok, *srow;
    cudaGetSymbolAddress((void**)&xn,   g_xn);
    cudaGetSymbolAddress((void**)&qkv,  g_qkv);
    cudaGetSymbolAddress((void**)&attn, g_attn);
    cudaGetSymbolAddress((void**)&x1,   g_x1);
    cudaGetSymbolAddress((void**)&xn2,  g_xn2);
    cudaGetSymbolAddress((void**)&fe,   g_fe);
    cudaGetSymbolAddress((void**)&fg,   g_fg);
    cudaGetSymbolAddress((void**)&cnt,  g_cnt);
    cudaGetSymbolAddress((void**)&esl,  g_esl);
    cudaGetSymbolAddress((void**)&egt,  g_egt);
    cudaGetSymbolAddress((void**)&dtok, g_dtok);
    cudaGetSymbolAddress((void**)&srow, g_srow);
    cudaGetSymbolAddress((void**)&xe,   g_xe);
    cudaGetSymbolAddress((void**)&h,    g_h);
    cudaGetSymbolAddress((void**)&ye,   g_ye);

    static bool attr_set = false;
    if (!attr_set) {
        cudaFuncSetAttribute(attn_tc,   cudaFuncAttributeMaxDynamicSharedMemorySize, AT_SMEM);
        cudaFuncSetAttribute(gemm_tf32, cudaFuncAttributeMaxDynamicSharedMemorySize, GSMEM);
        attr_set = true;
    }

    // attention branch
    rmsnorm_k<<<TT, 256>>>(x, g1, xn);
    gemm_tf32<<<dim3(3*DD/GBN, TT/GBM, 1), 256, GSMEM>>>(xn, w_qkv, qkv, nullptr,
                                                         TT, 3*DD, DD, 0, 0, 0, 0);
    rope_k<<<TT, 256>>>(qkv);
    attn_tc<<<dim3(SS/64, BB*HH), 128, AT_SMEM>>>(qkv, attn);
    gemm_tf32<<<dim3(DD/GBN, TT/GBM, 1), 256, GSMEM>>>(attn, w_o, x1, x,
                                                       TT, DD, DD, 0, 0, 0, 0);

    // MoE branch
    rmsnorm_k<<<TT, 256>>>(x1, g2, xn2);
    router_k<<<TT, 256>>>(xn2, w_router, fe, fg);
    zero_k<<<1, 32>>>(cnt);
    assign_k<<<NS/256, 256>>>(fe, fg, cnt, esl, egt);
    select_k<<<NE, 512>>>(cnt, esl, egt, dtok, srow);
    gather_k<<<NE*CAPN, 256>>>(dtok, xn2, xe);
    gemm_tf32<<<dim3(FFND/GBN, CAPN/GBM, NE), 256, GSMEM>>>(xe, w1, h, nullptr,
        CAPN, FFND, DD, (long long)CAPN*DD, (long long)DD*FFND, (long long)CAPN*FFND, 1);
    gemm_tf32<<<dim3(DD/GBN, CAPN/GBM, NE), 256, GSMEM>>>(h, w2, ye, nullptr,
        CAPN, DD, FFND, (long long)CAPN*FFND, (long long)FFND*DD, (long long)CAPN*DD, 0);
    combine_k<<<TT, 256>>>(x1, ye, srow, fg, out);
}

// round 8
// speedup vs baseline: 3.3533x; 1.0298x over previous
#include <cuda_runtime.h>
#include <math.h>
#include <stdint.h>

#define BB   2
#define SS   2048
#define DD   1024
#define HH   16
#define HDIM 64
#define FFND 2048
#define NE   8
#define CAPN 1280
#define TT   (BB*SS)
#define NS   (TT*2)

// ---------------- scratch (device globals; no allocations) ----------------
__device__ float g_xn  [TT*DD];
__device__ float g_qkv [TT*3*DD];
__device__ float g_attn[TT*DD];
__device__ float g_x1  [TT*DD];
__device__ float g_xn2 [TT*DD];
__device__ int   g_fe  [NS];
__device__ float g_fg  [NS];
__device__ int   g_cnt [NE];
__device__ int   g_esl [NE*NS];
__device__ float g_egt [NE*NS];
__device__ int   g_dtok[NE*CAPN];
__device__ int   g_srow[NS];
__device__ float g_xe  [NE*CAPN*DD];
__device__ float g_h   [NE*CAPN*FFND];
__device__ float g_ye  [NE*CAPN*DD];

// ---------------- helpers ----------------
__device__ __forceinline__ uint32_t f2tf32(float x) {
    uint32_t y;
    asm("cvt.rna.tf32.f32 %0, %1;" : "=r"(y) : "f"(x));
    return y;
}
__device__ __forceinline__ float tf32r(float x) {      // round to tf32 grid, as fp32
    return __uint_as_float(f2tf32(x));
}
__device__ __forceinline__ void mma_tf32(float* d, const uint32_t* a, const uint32_t* b) {
    asm volatile(
        "mma.sync.aligned.m16n8k8.row.col.f32.tf32.tf32.f32 "
        "{%0,%1,%2,%3},{%4,%5,%6,%7},{%8,%9},{%0,%1,%2,%3};\n"
        : "+f"(d[0]), "+f"(d[1]), "+f"(d[2]), "+f"(d[3])
        : "r"(a[0]), "r"(a[1]), "r"(a[2]), "r"(a[3]), "r"(b[0]), "r"(b[1]));
}
__device__ __forceinline__ void cp16(uint32_t s, const void* g) {
    asm volatile("cp.async.cg.shared.global [%0], [%1], 16;\n" :: "r"(s), "l"(g));
}
__device__ __forceinline__ void cp_commit() { asm volatile("cp.async.commit_group;\n"); }
template<int N> __device__ __forceinline__ void cp_wait() {
    asm volatile("cp.async.wait_group %0;\n" :: "n"(N));
}
// fast exp on FMA pipe; rel err ~2e-7
__device__ __forceinline__ float fast_exp(float x) {
    float y = fmaxf(x * 1.4426950408889634f, -126.f);
    float n = floorf(y);
    float f = y - n;
    float p =              1.8775767e-3f;
    p = fmaf(p, f, 8.9893397e-3f);
    p = fmaf(p, f, 5.5826318e-2f);
    p = fmaf(p, f, 2.4015361e-1f);
    p = fmaf(p, f, 6.9315308e-1f);
    p = fmaf(p, f, 9.9999994e-1f);
    return __int_as_float(__float_as_int(p) + (((int)n) << 23));
}

// ---------------- rmsnorm ----------------
__global__ void rmsnorm_k(const float* __restrict__ in, const float* __restrict__ g,
                          float* __restrict__ out) {
    int t = blockIdx.x;
    const float4* xi = (const float4*)(in + (size_t)t * DD);
    float4 v = xi[threadIdx.x];
    float ss = v.x*v.x + v.y*v.y + v.z*v.z + v.w*v.w;
    __shared__ float red[256];
    red[threadIdx.x] = ss;
    __syncthreads();
    for (int s = 128; s > 0; s >>= 1) {
        if (threadIdx.x < s) red[threadIdx.x] += red[threadIdx.x + s];
        __syncthreads();
    }
    float rms = rsqrtf(red[0] / (float)DD + 1e-6f);
    float4 gv = ((const float4*)g)[threadIdx.x];
    float4 o;
    o.x = v.x * gv.x * rms; o.y = v.y * gv.y * rms;
    o.z = v.z * gv.z * rms; o.w = v.w * gv.w * rms;
    ((float4*)(out + (size_t)t * DD))[threadIdx.x] = o;
}

// ---------------- tf32 GEMM: 128x128x16, 4-stage cp.async, single sync --------
#define GBM 128
#define GBN 128
#define GBK 16
#define ST    4
#define AROW  20
#define BROW  136
#define AW    (GBM*AROW)
#define BW    (GBK*BROW)
#define STW   (AW+BW)
#define GSMEM (ST*STW*4)

__global__ __launch_bounds__(256) void gemm_tf32(
    const float* __restrict__ A, const float* __restrict__ B, float* __restrict__ C,
    const float* __restrict__ addend, int M, int N, int K,
    long long sA, long long sB, long long sC, int relu)
{
    int e = blockIdx.z;
    A += (size_t)e * sA; B += (size_t)e * sB; C += (size_t)e * sC;

    extern __shared__ float smem[];
    uint32_t smem_base = (uint32_t)__cvta_generic_to_shared(smem);

    int tid  = threadIdx.x;
    int warp = tid >> 5, lane = tid & 31;
    int wm = (warp >> 1) * 32;
    int wn = (warp & 1) * 64;
    int r  = lane >> 2, c = lane & 3;

    int rowb = blockIdx.y * GBM, colb = blockIdx.x * GBN;

    int a_r0 = tid >> 2,           a_q0 = tid & 3;
    int a_r1 = (tid + 256) >> 2,   a_q1 = tid & 3;
    int b_k0 = tid >> 5,           b_q0 = tid & 31;
    int b_k1 = (tid + 256) >> 5,   b_q1 = tid & 31;

    float acc[2][8][4];
    #pragma unroll
    for (int mi = 0; mi < 2; mi++)
        #pragma unroll
        for (int ni = 0; ni < 8; ni++)
            #pragma unroll
            for (int q = 0; q < 4; q++) acc[mi][ni][q] = 0.f;

    int nk = K / GBK;

    auto issue = [&](int stage, int kt) {
        uint32_t sa = smem_base + stage * (STW * 4);
        uint32_t sb = sa + AW * 4;
        int k0 = kt * GBK;
        cp16(sa + (a_r0*AROW + a_q0*4)*4, A + (size_t)(rowb + a_r0)*K + k0 + a_q0*4);
        cp16(sa + (a_r1*AROW + a_q1*4)*4, A + (size_t)(rowb + a_r1)*K + k0 + a_q1*4);
        cp16(sb + (b_k0*BROW + b_q0*4)*4, B + (size_t)(k0 + b_k0)*N + colb + b_q0*4);
        cp16(sb + (b_k1*BROW + b_q1*4)*4, B + (size_t)(k0 + b_k1)*N + colb + b_q1*4);
    };

    int pre = (nk < ST-1) ? nk : ST-1;
    for (int s = 0; s < pre; s++) { issue(s, s); cp_commit(); }
    for (int s = pre; s < ST-1; s++) cp_commit();

    for (int kt = 0; kt < nk; kt++) {
        cp_wait<ST-2>();
        __syncthreads();

        int nx = kt + ST - 1;
        if (nx < nk) issue(nx % ST, nx);
        cp_commit();

        int stage = kt % ST;
        const uint32_t* As = (const uint32_t*)(smem + stage * STW);
        const uint32_t* Bs = (const uint32_t*)(smem + stage * STW + AW);

        #pragma unroll
        for (int ks = 0; ks < GBK; ks += 8) {
            uint32_t af[2][4];
            #pragma unroll
            for (int mi = 0; mi < 2; mi++) {
                int m = wm + mi * 16 + r;
                af[mi][0] = As[ m      *AROW + ks + c    ];
                af[mi][1] = As[(m + 8)*AROW + ks + c    ];
                af[mi][2] = As[ m      *AROW + ks + c + 4];
                af[mi][3] = As[(m + 8)*AROW + ks + c + 4];
            }
            #pragma unroll
            for (int ni = 0; ni < 8; ni++) {
                uint32_t bf[2];
                int n = wn + ni * 8 + r;
                bf[0] = Bs[(ks + c    )*BROW + n];
                bf[1] = Bs[(ks + c + 4)*BROW + n];
                mma_tf32(acc[0][ni], af[0], bf);
                mma_tf32(acc[1][ni], af[1], bf);
            }
        }
    }

    #pragma unroll
    for (int mi = 0; mi < 2; mi++) {
        #pragma unroll
        for (int ni = 0; ni < 8; ni++) {
            int row = rowb + wm + mi * 16 + r;
            int col = colb + wn + ni * 8 + 2 * c;
            size_t i0 = (size_t)row * N + col;
            size_t i1 = (size_t)(row + 8) * N + col;
            float2 v0 = make_float2(acc[mi][ni][0], acc[mi][ni][1]);
            float2 v1 = make_float2(acc[mi][ni][2], acc[mi][ni][3]);
            if (addend) {
                float2 d0 = *(const float2*)(addend + i0);
                float2 d1 = *(const float2*)(addend + i1);
                v0.x += d0.x; v0.y += d0.y; v1.x += d1.x; v1.y += d1.y;
            }
            if (relu) {
                v0.x = fmaxf(v0.x, 0.f); v0.y = fmaxf(v0.y, 0.f);
                v1.x = fmaxf(v1.x, 0.f); v1.y = fmaxf(v1.y, 0.f);
            }
            *(float2*)(C + i0) = v0;
            *(float2*)(C + i1) = v1;
        }
    }
}

// ---------------- RoPE + tf32 pre-round of q,k,v (in place) ----------------
// After this kernel every element of q,k,v lies on the tf32 grid, so the MMA's
// RZ truncation in attention is exact (numerics identical to rna conversion).
__global__ void rope_k(float* __restrict__ qkv) {
    int t = blockIdx.x;
    int s = t % SS;
    for (int w = threadIdx.x; w < 1024; w += blockDim.x) {
        int which = w >> 9;
        int rem   = w & 511;
        int h     = rem >> 5;
        int i     = rem & 31;
        float theta = exp2f(-(float)i * 0.41524101186092030f);
        float fr = (float)s * theta;
        float cc, sn;
        __sincosf(fr, &sn, &cc);
        size_t base = (size_t)t * (3*DD) + (size_t)which * DD + h * HDIM + 2*i;
        float xr = qkv[base], xi = qkv[base+1];
        qkv[base]   = tf32r(xr*cc - xi*sn);
        qkv[base+1] = tf32r(xr*sn + xi*cc);
    }
    // pre-round v
    float4* vp = (float4*)(qkv + (size_t)t * (3*DD) + 2*DD);
    float4 v = vp[threadIdx.x];
    v.x = tf32r(v.x); v.y = tf32r(v.y); v.z = tf32r(v.z); v.w = tf32r(v.w);
    vp[threadIdx.x] = v;
}

// ---------------- tensor-core flash attention, cp.async double-buffered -------
// smem words: Qs/Ps 4352 | K0 4352 | K1 4352 | V0 4352 | V1 4352
#define AT_SMEM (5 * 4352 * 4)

__global__ __launch_bounds__(128) void attn_tc(const float* __restrict__ qkv,
                                               float* __restrict__ out) {
    extern __shared__ uint32_t sm[];
    uint32_t* Qs = sm;
    uint32_t smem_base = (uint32_t)__cvta_generic_to_shared(sm);

    int qt = gridDim.x - 1 - blockIdx.x;     // longest blocks first
    int bh = blockIdx.y;
    int b = bh >> 4, h = bh & 15;
    int tid = threadIdx.x, warp = tid >> 5, lane = tid & 31;
    int r = lane >> 2, c = lane & 3;
    int qb = qt * 64;
    const size_t RS = 3 * DD;
    const float scale = 0.125f;

    auto issue = [&](int st, int kt) {
        uint32_t kbase = smem_base + (4352 + st*4352) * 4;
        uint32_t vbase = smem_base + (13056 + st*4352) * 4;
        const float* src = qkv + (size_t)(b*SS + kt*64) * RS + h*HDIM;
        #pragma unroll
        for (int u = tid; u < 1024; u += 128) {
            int row = u >> 4, q = (u & 15) * 4;
            size_t off = (size_t)row * RS + q;
            cp16(kbase + (row*68 + q)*4, src + DD   + off);
            cp16(vbase + (row*68 + q)*4, src + 2*DD + off);
        }
    };
    issue(0, 0);
    cp_commit();

    // ---- stage Q tile transposed (scaled; values pre-rounded, scale exact) ----
    for (int u = tid; u < 1024; u += 128) {
        int row = u >> 4, d4 = (u & 15) * 4;
        float4 v = *(const float4*)(qkv + (size_t)(b*SS + qb + row) * RS + h*HDIM + d4);
        Qs[(d4+0)*68 + row] = __float_as_uint(v.x * scale);
        Qs[(d4+1)*68 + row] = __float_as_uint(v.y * scale);
        Qs[(d4+2)*68 + row] = __float_as_uint(v.z * scale);
        Qs[(d4+3)*68 + row] = __float_as_uint(v.w * scale);
    }
    __syncthreads();

    int mb = warp * 16;
    uint32_t qf[8][4];
    #pragma unroll
    for (int ks = 0; ks < 8; ks++) {
        int k0 = ks * 8;
        qf[ks][0] = Qs[(k0 + c    )*68 + mb + r];
        qf[ks][1] = Qs[(k0 + c    )*68 + mb + r + 8];
        qf[ks][2] = Qs[(k0 + c + 4)*68 + mb + r];
        qf[ks][3] = Qs[(k0 + c + 4)*68 + mb + r + 8];
    }

    uint32_t* Ps = Qs + warp * 1088;

    float oacc[8][4];
    #pragma unroll
    for (int ni = 0; ni < 8; ni++)
        #pragma unroll
        for (int q = 0; q < 4; q++) oacc[ni][q] = 0.f;
    float m0 = -INFINITY, m1 = -INFINITY, l0 = 0.f, l1 = 0.f;

    int row0 = qb + mb + r, row1 = row0 + 8;

    for (int kt = 0; kt <= qt; kt++) {
        __syncthreads();                   // prior compute on overwritten stage done
        if (kt + 1 <= qt) issue((kt + 1) & 1, kt + 1);
        cp_commit();
        cp_wait<1>();
        __syncthreads();                   // tile kt visible

        const uint32_t* Kst = sm + 4352  + (kt & 1) * 4352;
        const uint32_t* Vst = sm + 13056 + (kt & 1) * 4352;

        // ---- S = Q K^T ----
        float s[8][4];
        #pragma unroll
        for (int ni = 0; ni < 8; ni++) {
            float sa[4] = {0.f, 0.f, 0.f, 0.f};
            const uint32_t* kr = Kst + (ni*8 + r) * 68;
            #pragma unroll
            for (int ks = 0; ks < 8; ks++) {
                uint32_t bf[2];
                bf[0] = kr[ks*8 + c];
                bf[1] = kr[ks*8 + c + 4];
                mma_tf32(sa, qf[ks], bf);
            }
            s[ni][0] = sa[0]; s[ni][1] = sa[1]; s[ni][2] = sa[2]; s[ni][3] = sa[3];
        }

        if (kt == qt) {
            #pragma unroll
            for (int ni = 0; ni < 8; ni++) {
                int col = kt*64 + ni*8 + 2*c;
                if (col     > row0) s[ni][0] = -1e30f;
                if (col + 1 > row0) s[ni][1] = -1e30f;
                if (col     > row1) s[ni][2] = -1e30f;
                if (col + 1 > row1) s[ni][3] = -1e30f;
            }
        }

        float mx0 = -1e30f, mx1 = -1e30f;
        #pragma unroll
        for (int ni = 0; ni < 8; ni++) {
            mx0 = fmaxf(mx0, fmaxf(s[ni][0], s[ni][1]));
            mx1 = fmaxf(mx1, fmaxf(s[ni][2], s[ni][3]));
        }
        mx0 = fmaxf(mx0, __shfl_xor_sync(0xffffffff, mx0, 1));
        mx0 = fmaxf(mx0, __shfl_xor_sync(0xffffffff, mx0, 2));
        mx1 = fmaxf(mx1, __shfl_xor_sync(0xffffffff, mx1, 1));
        mx1 = fmaxf(mx1, __shfl_xor_sync(0xffffffff, mx1, 2));
        float mn0 = fmaxf(m0, mx0), mn1 = fmaxf(m1, mx1);
        float cor0 = fast_exp(m0 - mn0), cor1 = fast_exp(m1 - mn1);
        m0 = mn0; m1 = mn1;

        float ls0 = 0.f, ls1 = 0.f;
        #pragma unroll
        for (int ni = 0; ni < 8; ni++) {
            float p0 = fast_exp(s[ni][0] - mn0);
            float p1 = fast_exp(s[ni][1] - mn0);
            float p2 = fast_exp(s[ni][2] - mn1);
            float p3 = fast_exp(s[ni][3] - mn1);
            ls0 += p0 + p1; ls1 += p2 + p3;
            int kc = ni*8 + 2*c;
            Ps[(kc    )*17 + r    ] = f2tf32(p0);
            Ps[(kc + 1)*17 + r    ] = f2tf32(p1);
            Ps[(kc    )*17 + r + 8] = f2tf32(p2);
            Ps[(kc + 1)*17 + r + 8] = f2tf32(p3);
        }
        ls0 += __shfl_xor_sync(0xffffffff, ls0, 1);
        ls0 += __shfl_xor_sync(0xffffffff, ls0, 2);
        ls1 += __shfl_xor_sync(0xffffffff, ls1, 1);
        ls1 += __shfl_xor_sync(0xffffffff, ls1, 2);
        l0 = l0 * cor0 + ls0;
        l1 = l1 * cor1 + ls1;

        #pragma unroll
        for (int ni = 0; ni < 8; ni++) {
            oacc[ni][0] *= cor0; oacc[ni][1] *= cor0;
            oacc[ni][2] *= cor1; oacc[ni][3] *= cor1;
        }
        __syncwarp();

        #pragma unroll
        for (int ks = 0; ks < 8; ks++) {
            int k0 = ks * 8;
            uint32_t af[4];
            af[0] = Ps[(k0 + c    )*17 + r];
            af[1] = Ps[(k0 + c    )*17 + r + 8];
            af[2] = Ps[(k0 + c + 4)*17 + r];
            af[3] = Ps[(k0 + c + 4)*17 + r + 8];
            #pragma unroll
            for (int ni = 0; ni < 8; ni++) {
                uint32_t bf[2];
                bf[0] = Vst[(k0 + c    )*68 + ni*8 + r];
                bf[1] = Vst[(k0 + c + 4)*68 + ni*8 + r];
                mma_tf32(oacc[ni], af, bf);
            }
        }
        __syncwarp();
    }

    float inv0 = 1.f / l0, inv1 = 1.f / l1;
    #pragma unroll
    for (int ni = 0; ni < 8; ni++) {
        int col = h*HDIM + ni*8 + 2*c;
        *(float2*)(out + (size_t)(b*SS + row0) * DD + col) =
            make_float2(oacc[ni][0]*inv0, oacc[ni][1]*inv0);
        *(float2*)(out + (size_t)(b*SS + row1) * DD + col) =
            make_float2(oacc[ni][2]*inv1, oacc[ni][3]*inv1);
    }
}

// ---------------- router ----------------
__global__ void router_k(const float* __restrict__ xn, const float* __restrict__ wr,
                         int* __restrict__ fe, float* __restrict__ fg) {
    int t = blockIdx.x;
    int lane = threadIdx.x & 31, w = threadIdx.x >> 5;
    const float* xr = xn + (size_t)t * DD;
    float p = 0.f;
    for (int d = lane; d < DD; d += 32) p += xr[d] * wr[(size_t)d * NE + w];
    #pragma unroll
    for (int o = 16; o > 0; o >>= 1) p += __shfl_xor_sync(0xffffffff, p, o);
    __shared__ float lg[NE];
    if (lane == 0) lg[w] = p;
    __syncthreads();
    if (threadIdx.x == 0) {
        float mx = lg[0];
        for (int e = 1; e < NE; e++) mx = fmaxf(mx, lg[e]);
        float pr[NE], sum = 0.f;
        for (int e = 0; e < NE; e++) { pr[e] = expf(lg[e] - mx); sum += pr[e]; }
        float inv = 1.f / sum;
        int e1 = 0; float v1 = pr[0];
        for (int e = 1; e < NE; e++) if (pr[e] > v1) { v1 = pr[e]; e1 = e; }
        int e2 = -1; float v2 = -INFINITY;
        for (int e = 0; e < NE; e++) {
            if (e == e1) continue;
            if (pr[e] > v2) { v2 = pr[e]; e2 = e; }
        }
        fe[2*t]   = e1; fg[2*t]   = v1 * inv;
        fe[2*t+1] = e2; fg[2*t+1] = v2 * inv;
    }
}

__global__ void zero_k(int* cnt) { if (threadIdx.x < NE) cnt[threadIdx.x] = 0; }

__global__ void assign_k(const int* __restrict__ fe, const float* __restrict__ fg,
                         int* __restrict__ cnt, int* __restrict__ esl,
                         float* __restrict__ egt) {
    int s = blockIdx.x * blockDim.x + threadIdx.x;
    if (s >= NS) return;
    int e = fe[s];
    int p = atomicAdd(&cnt[e], 1);
    esl[e*NS + p] = s;
    egt[e*NS + p] = fg[s];
}

__global__ void select_k(const int* __restrict__ cnt, const int* __restrict__ esl,
                         const float* __restrict__ egt, int* __restrict__ dtok,
                         int* __restrict__ srow) {
    int e = blockIdx.x;
    int n = cnt[e];
    const int*   sl = esl + e*NS;
    const float* gt = egt + e*NS;
    for (int i = threadIdx.x; i < n; i += blockDim.x) {
        float gi = gt[i]; int si = sl[i];
        int rank = 0;
        for (int j = 0; j < n; j++) {
            float gj = gt[j]; int sj = sl[j];
            rank += (gj > gi) || (gj == gi && sj < si);
        }
        if (rank < CAPN) {
            dtok[e*CAPN + rank] = si >> 1;
            srow[si] = e*CAPN + rank;
        } else srow[si] = -1;
    }
    for (int rr = n + threadIdx.x; rr < CAPN; rr += blockDim.x) dtok[e*CAPN + rr] = 0;
}

__global__ void gather_k(const int* __restrict__ dtok, const float* __restrict__ xn2,
                         float* __restrict__ xe) {
    int R = blockIdx.x;
    int tok = dtok[R];
    ((float4*)(xe + (size_t)R * DD))[threadIdx.x] =
        ((const float4*)(xn2 + (size_t)tok * DD))[threadIdx.x];
}

__global__ void combine_k(const float* __restrict__ x1, const float* __restrict__ ye,
                          const int* __restrict__ srow, const float* __restrict__ fg,
                          float* __restrict__ out) {
    int t = blockIdx.x;
    float4 o = ((const float4*)(x1 + (size_t)t * DD))[threadIdx.x];
    #pragma unroll
    for (int k = 0; k < 2; k++) {
        int s = 2*t + k;
        int rr = srow[s];
        if (rr >= 0) {
            float gg = fg[s];
            float4 y = ((const float4*)(ye + (size_t)rr * DD))[threadIdx.x];
            o.x += gg*y.x; o.y += gg*y.y; o.z += gg*y.z; o.w += gg*y.w;
        }
    }
    ((float4*)(out + (size_t)t * DD))[threadIdx.x] = o;
}

// ---------------- host ----------------
extern "C" void kernel_launch(void* const* d_in, const int* in_sizes, int n_in,
                              void* d_out, int out_size) {
    const float* x        = (const float*)d_in[0];
    const float* g1       = (const float*)d_in[1];
    const float* w_qkv    = (const float*)d_in[2];
    const float* w_o      = (const float*)d_in[3];
    const float* g2       = (const float*)d_in[4];
    const float* w_router = (const float*)d_in[5];
    const float* w1       = (const float*)d_in[6];
    const float* w2       = (const float*)d_in[7];
    float* out = (float*)d_out;

    float *xn, *qkv, *attn, *x1, *xn2, *fg, *egt, *xe, *h, *ye;
    int *fe, *cnt, *esl, *dtok, *srow;
    cudaGetSymbolAddress((void**)&xn,   g_xn);
    cudaGetSymbolAddress((void**)&qkv,  g_qkv);
    cudaGetSymbolAddress((void**)&attn, g_attn);
    cudaGetSymbolAddress((void**)&x1,   g_x1);
    cudaGetSymbolAddress((void**)&xn2,  g_xn2);
    cudaGetSymbolAddress((void**)&fe,   g_fe);
    cudaGetSymbolAddress((void**)&fg,   g_fg);
    cudaGetSymbolAddress((void**)&cnt,  g_cnt);
    cudaGetSymbolAddress((void**)&esl,  g_esl);
    cudaGetSymbolAddress((void**)&egt,  g_egt);
    cudaGetSymbolAddress((void**)&dtok, g_dtok);
    cudaGetSymbolAddress((void**)&srow, g_srow);
    cudaGetSymbolAddress((void**)&xe,   g_xe);
    cudaGetSymbolAddress((void**)&h,    g_h);
    cudaGetSymbolAddress((void**)&ye,   g_ye);

    static bool attr_set = false;
    if (!attr_set) {
        cudaFuncSetAttribute(attn_tc,   cudaFuncAttributeMaxDynamicSharedMemorySize, AT_SMEM);
        cudaFuncSetAttribute(gemm_tf32, cudaFuncAttributeMaxDynamicSharedMemorySize, GSMEM);
        attr_set = true;
    }

    // attention branch
    rmsnorm_k<<<TT, 256>>>(x, g1, xn);
    gemm_tf32<<<dim3(3*DD/GBN, TT/GBM, 1), 256, GSMEM>>>(xn, w_qkv, qkv, nullptr,
                                                         TT, 3*DD, DD, 0, 0, 0, 0);
    rope_k<<<TT, 256>>>(qkv);
    attn_tc<<<dim3(SS/64, BB*HH), 128, AT_SMEM>>>(qkv, attn);
    gemm_tf32<<<dim3(DD/GBN, TT/GBM, 1), 256, GSMEM>>>(attn, w_o, x1, x,
                                                       TT, DD, DD, 0, 0, 0, 0);

    // MoE branch
    rmsnorm_k<<<TT, 256>>>(x1, g2, xn2);
    router_k<<<TT, 256>>>(xn2, w_router, fe, fg);
    zero_k<<<1, 32>>>(cnt);
    assign_k<<<NS/256, 256>>>(fe, fg, cnt, esl, egt);
    select_k<<<NE, 512>>>(cnt, esl, egt, dtok, srow);
    gather_k<<<NE*CAPN, 256>>>(dtok, xn2, xe);
    gemm_tf32<<<dim3(FFND/GBN, CAPN/GBM, NE), 256, GSMEM>>>(xe, w1, h, nullptr,
        CAPN, FFND, DD, (long long)CAPN*DD, (long long)DD*FFND, (long long)CAPN*FFND, 1);
    gemm_tf32<<<dim3(DD/GBN, CAPN/GBM, NE), 256, GSMEM>>>(h, w2, ye, nullptr,
        CAPN, DD, FFND, (long long)CAPN*FFND, (long long)FFND*DD, (long long)CAPN*DD, 0);
    combine_k<<<TT, 256>>>(x1, ye, srow, fg, out);
}